// round 8
// baseline (speedup 1.0000x reference)
#include <cuda_runtime.h>
#include <cuda_bf16.h>
#include <cuda_fp16.h>
#include <math.h>
#include <stdint.h>

#define NC      128       // persistent CTAs; CTA owns hidden slice j0 = bid*8
#define TSTEPS  512

// ---------------- scratch (__device__ globals; no runtime allocation) ------
__device__ float g_xi[(size_t)512 * 128 * 3072];     // [T][B][3H]
__device__ __half g_xhi[(size_t)128 * 512 * 512];    // x split hi (fp16)
__device__ __half g_xlo[(size_t)128 * 512 * 512];    // x split lo
__device__ __half g_wih[(size_t)512 * 3072];         // Wi fp16
__device__ __half g_hf[2][128 * 1024];               // h fp16 (ping-pong)
__device__ unsigned g_bar_count;
__device__ volatile unsigned g_bar_sense;

// ---------------- recurrence SMEM layout (dynamic, bytes) -------------------
// ws: W fragments fp16: [term2][ks64][gate3][lane32][reg2] u32 = 96KB
// A staging: per-warp private, 3 bufs x (32 rows x 272B) = 26112 B/warp
#define WS_OFF     0
#define WS_TERMSZ  49152
#define A_OFF      98304
#define A_BUF_SZ   8704          // 32 rows * 272B
#define A_WARP_SZ  26112         // 3 bufs
#define SMEM_TOTAL (98304 + 4 * 26112)   // 202752

// ---------------- xi mma SMEM layout (bytes) --------------------------------
#define XA_OFF   0
#define XA_TSZ   18432           // 128*144
#define XA_BUFSZ 36864           // 2 terms
#define XB_OFF   73728
#define XB_BUFSZ 9216            // 64*144
#define SMEM_XI  92160

// ---------------- PTX helpers ------------------------------------------------
__device__ __forceinline__ void mma_f16(float* c, const uint32_t* a,
                                        uint32_t b0, uint32_t b1) {
    asm volatile(
        "mma.sync.aligned.m16n8k16.row.col.f32.f16.f16.f32 "
        "{%0,%1,%2,%3}, {%4,%5,%6,%7}, {%8,%9}, {%0,%1,%2,%3};"
        : "+f"(c[0]), "+f"(c[1]), "+f"(c[2]), "+f"(c[3])
        : "r"(a[0]), "r"(a[1]), "r"(a[2]), "r"(a[3]), "r"(b0), "r"(b1));
}

__device__ __forceinline__ void ldmatrix_x4(uint32_t* a, uint32_t addr) {
    asm volatile(
        "ldmatrix.sync.aligned.m8n8.x4.shared.b16 {%0,%1,%2,%3}, [%4];"
        : "=r"(a[0]), "=r"(a[1]), "=r"(a[2]), "=r"(a[3]) : "r"(addr));
}

__device__ __forceinline__ void ldmatrix_x2t(uint32_t& b0, uint32_t& b1,
                                             uint32_t addr) {
    asm volatile(
        "ldmatrix.sync.aligned.m8n8.x2.trans.shared.b16 {%0,%1}, [%2];"
        : "=r"(b0), "=r"(b1) : "r"(addr));
}

__device__ __forceinline__ void cp16(uint32_t dst, const void* src) {
    asm volatile("cp.async.cg.shared.global [%0], [%1], 16;"
                 :: "r"(dst), "l"(src) : "memory");
}

// ---------------- prep: split x into fp16 hi/lo ------------------------------
__global__ __launch_bounds__(256) void split_x(const float* __restrict__ x)
{
    const size_t i = (size_t)blockIdx.x * 256 + threadIdx.x;
    const float v = x[i];
    const __half hi = __float2half_rn(v);
    g_xhi[i] = hi;
    g_xlo[i] = __float2half_rn(v - __half2float(hi));
}

// ---------------- prep: Wi -> fp16 -------------------------------------------
__global__ __launch_bounds__(256) void split_wi(const float* __restrict__ Wi)
{
    const size_t i = (size_t)blockIdx.x * 256 + threadIdx.x;
    g_wih[i] = __float2half_rn(Wi[i]);
}

// ---------------- xi = x @ Wi + bi  via mma.sync fp16 2-term -----------------
// (unchanged, validated)
__global__ __launch_bounds__(256, 2) void xi_mma(
    const float* __restrict__ bi, float* __restrict__ xi)
{
    extern __shared__ char sm[];
    const uint32_t su = (uint32_t)__cvta_generic_to_shared(sm);

    const int tid  = threadIdx.x;
    const int wid  = tid >> 5;
    const int lane = tid & 31;
    const int t    = blockIdx.y;
    const int n0   = blockIdx.x * 64;
    const int wm   = wid >> 1;
    const int wn   = wid & 1;

    float acc[2][4][4];
#pragma unroll
    for (int i = 0; i < 2; i++)
#pragma unroll
        for (int j = 0; j < 4; j++)
#pragma unroll
            for (int p = 0; p < 4; p++) acc[i][j][p] = 0.f;

    {
        const uint32_t ab = su + XA_OFF;
#pragma unroll
        for (int it = 0; it < 8; it++) {
            const int idx = tid + it * 256;
            const int term = idx >> 10;
            const int r = (idx >> 3) & 127;
            const int off = idx & 7;
            const __half* src = term ? g_xlo : g_xhi;
            cp16(ab + term * XA_TSZ + r * 144 + off * 16,
                 &src[((size_t)r * 512 + t) * 512 + off * 8]);
        }
#pragma unroll
        for (int it = 0; it < 2; it++) {
            const int idx = tid + it * 256;
            const int r = idx >> 3, off = idx & 7;
            cp16(su + XB_OFF + r * 144 + off * 16,
                 &g_wih[(size_t)r * 3072 + n0 + off * 8]);
        }
        asm volatile("cp.async.commit_group;" ::: "memory");
    }

#pragma unroll 1
    for (int c = 0; c < 8; c++) {
        asm volatile("cp.async.wait_group 0;" ::: "memory");
        __syncthreads();

        if (c < 7) {
            const int nb = (c + 1) & 1;
            const int kb = (c + 1) * 64;
            const uint32_t ab = su + XA_OFF + nb * XA_BUFSZ;
#pragma unroll
            for (int it = 0; it < 8; it++) {
                const int idx = tid + it * 256;
                const int term = idx >> 10;
                const int r = (idx >> 3) & 127;
                const int off = idx & 7;
                const __half* src = term ? g_xlo : g_xhi;
                cp16(ab + term * XA_TSZ + r * 144 + off * 16,
                     &src[((size_t)r * 512 + t) * 512 + kb + off * 8]);
            }
#pragma unroll
            for (int it = 0; it < 2; it++) {
                const int idx = tid + it * 256;
                const int r = idx >> 3, off = idx & 7;
                cp16(su + XB_OFF + nb * XB_BUFSZ + r * 144 + off * 16,
                     &g_wih[(size_t)(kb + r) * 3072 + n0 + off * 8]);
            }
            asm volatile("cp.async.commit_group;" ::: "memory");
        }

        const uint32_t abuf = su + XA_OFF + (c & 1) * XA_BUFSZ;
        const uint32_t bbuf = su + XB_OFF + (c & 1) * XB_BUFSZ;
#pragma unroll
        for (int kk = 0; kk < 4; kk++) {
            uint32_t a_hi[2][4], a_lo[2][4];
#pragma unroll
            for (int tile = 0; tile < 2; tile++) {
                const uint32_t aaddr = abuf
                    + (wm * 32 + tile * 16 + (lane & 15)) * 144
                    + (lane >> 4) * 16 + kk * 32;
                ldmatrix_x4(a_hi[tile], aaddr);
                ldmatrix_x4(a_lo[tile], aaddr + XA_TSZ);
            }
            uint32_t bf[4][2];
#pragma unroll
            for (int nt = 0; nt < 4; nt++) {
                const uint32_t baddr = bbuf
                    + (kk * 16 + (lane & 15)) * 144
                    + (wn * 32 + nt * 8) * 2;
                ldmatrix_x2t(bf[nt][0], bf[nt][1], baddr);
            }
#pragma unroll
            for (int tile = 0; tile < 2; tile++)
#pragma unroll
                for (int nt = 0; nt < 4; nt++) {
                    mma_f16(acc[tile][nt], a_hi[tile], bf[nt][0], bf[nt][1]);
                    mma_f16(acc[tile][nt], a_lo[tile], bf[nt][0], bf[nt][1]);
                }
        }
    }

    const int grp = lane >> 2;
    const int nlo = (lane & 3) * 2;
#pragma unroll
    for (int nt = 0; nt < 4; nt++) {
        const int n = n0 + wn * 32 + nt * 8 + nlo;
        const float2 bv = *reinterpret_cast<const float2*>(&bi[n]);
#pragma unroll
        for (int tile = 0; tile < 2; tile++) {
#pragma unroll
            for (int half = 0; half < 2; half++) {
                const int b = wm * 32 + tile * 16 + grp + half * 8;
                float2 o;
                o.x = acc[tile][nt][half * 2 + 0] + bv.x;
                o.y = acc[tile][nt][half * 2 + 1] + bv.y;
                *reinterpret_cast<float2*>(
                    &xi[((size_t)t * 128 + b) * 3072 + n]) = o;
            }
        }
    }
}

// ---------------- init: zero h buffer 0 + reset barrier ---------------------
__global__ void init_state()
{
    const int idx = blockIdx.x * 256 + threadIdx.x;   // < 131072
    g_hf[0][idx] = __float2half(0.f);
    if (idx == 0) { g_bar_count = 0; g_bar_sense = 0; }
}

// ---------------- grid barrier ----------------------------------------------
__device__ __forceinline__ void grid_barrier(unsigned& sense)
{
    __syncthreads();
    if (threadIdx.x == 0) {
        const unsigned s = sense + 1;
        __threadfence();
        if (atomicAdd(&g_bar_count, 1u) == gridDim.x - 1) {
            atomicExch(&g_bar_count, 0u);
            __threadfence();
            g_bar_sense = s;
        } else {
            while (g_bar_sense != s) { __nanosleep(32); }
        }
        __threadfence();
        sense = s;
    }
    __syncthreads();
}

// ---------------- persistent mma.sync GRU recurrence (fp16 2-term) ----------
// 128 CTAs x 128 threads (4 warps). CTA owns j-slice j0 = bid*8 (3 gates,
// N=24). Warp w owns batch rows [w*32, w*32+32) = TWO m16 A-tiles, so every
// B fragment (identical across warps) is reused by 2 mma -> smem B traffic
// halves vs round-7 and the kernel returns to tensor-bound.
// A staging warp-private 3-stage cp.async (__syncwarp only); W fragments
// (fp16 hi+lo) formatted once into SMEM; h stored as single fp16.
__global__ __launch_bounds__(128, 1)
void gru_mma_persist(const float* __restrict__ Wh, const float* __restrict__ bh,
                     float* __restrict__ out)
{
    extern __shared__ char sm[];
    const uint32_t smem_u32 = (uint32_t)__cvta_generic_to_shared(sm);
    uint32_t* const ws = reinterpret_cast<uint32_t*>(sm + WS_OFF);

    const int tid  = threadIdx.x;
    const int wid  = tid >> 5;        // 0..3
    const int lane = tid & 31;
    const int bid  = blockIdx.x;
    const int j0   = bid * 8;

    // one-time: format Wh slice into fp16 mma B fragments (hi & lo terms)
    for (int idx = tid; idx < 24576; idx += 128) {
        const int r    = idx & 1;
        const int l    = (idx >> 1) & 31;
        const int rest = idx >> 6;
        const int tt   = rest % 3;
        const int kst  = rest / 3;
        const int ks   = kst & 63;
        const int term = kst >> 6;
        const int n = tt * 1024 + j0 + (l >> 2);
        const int k = ks * 16 + r * 8 + (l & 3) * 2;

        const float w0 = Wh[(size_t)k * 3072 + n];
        const float w1 = Wh[(size_t)(k + 1) * 3072 + n];
        const __half h0 = __float2half_rn(w0);
        const __half h1 = __float2half_rn(w1);
        __half e0, e1;
        if (term == 0) { e0 = h0; e1 = h1; }
        else {
            e0 = __float2half_rn(w0 - __half2float(h0));
            e1 = __float2half_rn(w1 - __half2float(h1));
        }
        ws[idx] = ((uint32_t)__half_as_ushort(e1) << 16)
                |  (uint32_t)__half_as_ushort(e0);
    }
    __syncthreads();

    const int brow = lane >> 2;            // 0..7
    const int jb   = j0 + (lane & 3) * 2;  // 2 cols per thread
    const int arow = wid * 32;             // this warp's first batch row

    float bhv[3][2];
#pragma unroll
    for (int g = 0; g < 3; g++) {
        bhv[g][0] = bh[g * 1024 + jb];
        bhv[g][1] = bh[g * 1024 + jb + 1];
    }

    float hp[2][2][2];   // [mtile][half][q]
#pragma unroll
    for (int m = 0; m < 2; m++)
#pragma unroll
        for (int hh = 0; hh < 2; hh++) { hp[m][hh][0] = 0.f; hp[m][hh][1] = 0.f; }

    const uint32_t awarp = smem_u32 + A_OFF + wid * A_WARP_SZ;
    unsigned sense = 0;

#pragma unroll 1
    for (int t = 0; t < TSTEPS; t++) {
        const float* __restrict__ xi_t = g_xi + (size_t)t * 128 * 3072;
        const __half* __restrict__ hs = g_hf[t & 1];
        __half* __restrict__ hd = g_hf[(t + 1) & 1];

        // xi prefetch into registers (overlaps with staging/mma)
        float xiv[3][2][2][2];   // [gate][mtile][half][q]
#pragma unroll
        for (int g = 0; g < 3; g++)
#pragma unroll
            for (int m = 0; m < 2; m++)
#pragma unroll
                for (int hh = 0; hh < 2; hh++) {
                    const int b = arow + m * 16 + brow + hh * 8;
                    const float2 v = *reinterpret_cast<const float2*>(
                        &xi_t[(size_t)b * 3072 + g * 1024 + jb]);
                    xiv[g][m][hh][0] = v.x; xiv[g][m][hh][1] = v.y;
                }

        float acc[3][2][4];
#pragma unroll
        for (int g = 0; g < 3; g++)
#pragma unroll
            for (int m = 0; m < 2; m++)
#pragma unroll
                for (int p = 0; p < 4; p++) acc[g][m][p] = 0.f;

        // prologue: stage chunks 0 and 1 (k-chunk = 128, 32 rows/warp)
#pragma unroll
        for (int pc = 0; pc < 2; pc++) {
            const uint32_t ab = awarp + pc * A_BUF_SZ;
#pragma unroll
            for (int it = 0; it < 16; it++) {
                const int idx = lane + it * 32;          // 0..511
                const int row = idx >> 4, off = idx & 15;
                cp16(ab + row * 272 + off * 16,
                     &hs[(arow + row) * 1024 + pc * 128 + off * 8]);
            }
            asm volatile("cp.async.commit_group;" ::: "memory");
        }

#pragma unroll 1
        for (int c = 0; c < 8; c++) {
            if (c < 6)
                asm volatile("cp.async.wait_group 1;" ::: "memory");
            else
                asm volatile("cp.async.wait_group 0;" ::: "memory");
            __syncwarp();

            const uint32_t abuf = awarp + (c % 3) * A_BUF_SZ;
#pragma unroll
            for (int kk = 0; kk < 8; kk++) {
                uint32_t a[2][4];
#pragma unroll
                for (int m = 0; m < 2; m++)
                    ldmatrix_x4(a[m], abuf + (m * 16 + (lane & 15)) * 272
                                     + (lane >> 4) * 16 + kk * 32);
                const int ks = c * 8 + kk;
#pragma unroll
                for (int tt = 0; tt < 3; tt++) {
                    const uint32_t boff = smem_u32 + WS_OFF
                                        + (uint32_t)((ks * 3 + tt) * 256) + lane * 8;
                    uint32_t bh0, bh1, bl0, bl1;
                    asm("ld.shared.v2.u32 {%0,%1}, [%2];"
                        : "=r"(bh0), "=r"(bh1) : "r"(boff));
                    asm("ld.shared.v2.u32 {%0,%1}, [%2];"
                        : "=r"(bl0), "=r"(bl1) : "r"(boff + WS_TERMSZ));
                    mma_f16(acc[tt][0], a[0], bh0, bh1);
                    mma_f16(acc[tt][1], a[1], bh0, bh1);
                    mma_f16(acc[tt][0], a[0], bl0, bl1);
                    mma_f16(acc[tt][1], a[1], bl0, bl1);
                }
            }

            if (c < 6) {   // stage chunk c+2
                const uint32_t ab = awarp + ((c + 2) % 3) * A_BUF_SZ;
                const int kb = (c + 2) * 128;
#pragma unroll
                for (int it = 0; it < 16; it++) {
                    const int idx = lane + it * 32;
                    const int row = idx >> 4, off = idx & 15;
                    cp16(ab + row * 272 + off * 16,
                         &hs[(arow + row) * 1024 + kb + off * 8]);
                }
                asm volatile("cp.async.commit_group;" ::: "memory");
            }
        }

        // ---------------- gate epilogue (registers only) ----------------
#pragma unroll
        for (int m = 0; m < 2; m++) {
#pragma unroll
            for (int hh = 0; hh < 2; hh++) {
                const int b = arow + m * 16 + brow + hh * 8;
                float hy2[2];
#pragma unroll
                for (int q = 0; q < 2; q++) {
                    const int p = hh * 2 + q;
                    const float hr = acc[0][m][p] + bhv[0][q];
                    const float hz = acc[1][m][p] + bhv[1][q];
                    const float hn = acc[2][m][p] + bhv[2][q];
                    const float rg = 1.f / (1.f + expf(-(xiv[0][m][hh][q] + hr)));
                    const float zg = 1.f / (1.f + expf(-(xiv[1][m][hh][q] + hz)));
                    const float ng = tanhf(xiv[2][m][hh][q] + rg * hn);
                    const float hy = zg * ng + (1.f - zg) * hp[m][hh][q];
                    hp[m][hh][q] = hy;
                    hy2[q] = hy;
                }
                const __half e0 = __float2half_rn(hy2[0]);
                const __half e1 = __float2half_rn(hy2[1]);
                *reinterpret_cast<uint32_t*>(&hd[b * 1024 + jb]) =
                    ((uint32_t)__half_as_ushort(e1) << 16)
                    | (uint32_t)__half_as_ushort(e0);
                if (t == TSTEPS - 1) {
                    float2 o; o.x = hy2[0]; o.y = hy2[1];
                    *reinterpret_cast<float2*>(&out[b * 1024 + jb]) = o;
                }
            }
        }

        if (t != TSTEPS - 1) grid_barrier(sense);
    }
}

// ---------------- launch ----------------------------------------------------
extern "C" void kernel_launch(void* const* d_in, const int* in_sizes, int n_in,
                              void* d_out, int out_size)
{
    const float* x  = (const float*)d_in[0];
    const float* Wi = (const float*)d_in[1];
    const float* bi = (const float*)d_in[2];
    const float* Wh = (const float*)d_in[3];
    const float* bh = (const float*)d_in[4];
    float* out = (float*)d_out;

    float* xi_ptr;
    cudaGetSymbolAddress((void**)&xi_ptr, g_xi);

    cudaFuncSetAttribute(gru_mma_persist,
                         cudaFuncAttributeMaxDynamicSharedMemorySize, SMEM_TOTAL);
    cudaFuncSetAttribute(xi_mma,
                         cudaFuncAttributeMaxDynamicSharedMemorySize, SMEM_XI);

    // prep: fp16 splits
    split_x<<<131072, 256>>>(x);
    split_wi<<<6144, 256>>>(Wi);
    // xi = x @ Wi + bi on tensor cores (fp16 2-term)
    xi_mma<<<dim3(48, 512), 256, SMEM_XI>>>(bi, xi_ptr);
    // zero h buffer + barrier
    init_state<<<512, 256>>>();
    // whole 512-step recurrence on tensor cores (fp16 2-term, B-frag reuse x2)
    gru_mma_persist<<<NC, 128, SMEM_TOTAL>>>(Wh, bh, out);
}

// round 9
// speedup vs baseline: 1.2921x; 1.2921x over previous
#include <cuda_runtime.h>
#include <cuda_bf16.h>
#include <cuda_fp16.h>
#include <math.h>
#include <stdint.h>

#define NC      128       // persistent CTAs; CTA owns hidden slice j0 = bid*8
#define TSTEPS  512

// ---------------- scratch (__device__ globals; no runtime allocation) ------
__device__ float g_xi[(size_t)512 * 128 * 3072];     // [T][B][3H]
__device__ __half g_xhi[(size_t)128 * 512 * 512];    // x split hi (fp16)
__device__ __half g_xlo[(size_t)128 * 512 * 512];    // x split lo
__device__ __half g_wih[(size_t)512 * 3072];         // Wi fp16
__device__ __half g_hf[2][128 * 1024];               // h fp16 (ping-pong)
__device__ unsigned g_bar_count;
__device__ volatile unsigned g_bar_sense;

// ---------------- recurrence SMEM layout (dynamic, bytes) -------------------
// ws: W fragments fp16 (single term): [ks64][gate3][lane32][reg2] u32 = 48KB
// A staging: per-warp private, 3 bufs x (16 rows x 272B) = 13056 B/warp
#define WS_OFF     0
#define A_OFF      49152
#define A_BUF_SZ   4352          // 16 rows * 272B
#define A_WARP_SZ  13056         // 3 bufs
#define SMEM_TOTAL (49152 + 8 * 13056)   // 153600

// ---------------- xi mma SMEM layout (bytes) --------------------------------
#define XA_OFF   0
#define XA_TSZ   18432           // 128*144
#define XA_BUFSZ 36864           // 2 terms
#define XB_OFF   73728
#define XB_BUFSZ 9216            // 64*144
#define SMEM_XI  92160

// ---------------- PTX helpers ------------------------------------------------
__device__ __forceinline__ void mma_f16(float* c, const uint32_t* a,
                                        uint32_t b0, uint32_t b1) {
    asm volatile(
        "mma.sync.aligned.m16n8k16.row.col.f32.f16.f16.f32 "
        "{%0,%1,%2,%3}, {%4,%5,%6,%7}, {%8,%9}, {%0,%1,%2,%3};"
        : "+f"(c[0]), "+f"(c[1]), "+f"(c[2]), "+f"(c[3])
        : "r"(a[0]), "r"(a[1]), "r"(a[2]), "r"(a[3]), "r"(b0), "r"(b1));
}

__device__ __forceinline__ void ldmatrix_x4(uint32_t* a, uint32_t addr) {
    asm volatile(
        "ldmatrix.sync.aligned.m8n8.x4.shared.b16 {%0,%1,%2,%3}, [%4];"
        : "=r"(a[0]), "=r"(a[1]), "=r"(a[2]), "=r"(a[3]) : "r"(addr));
}

__device__ __forceinline__ void ldmatrix_x2t(uint32_t& b0, uint32_t& b1,
                                             uint32_t addr) {
    asm volatile(
        "ldmatrix.sync.aligned.m8n8.x2.trans.shared.b16 {%0,%1}, [%2];"
        : "=r"(b0), "=r"(b1) : "r"(addr));
}

__device__ __forceinline__ void cp16(uint32_t dst, const void* src) {
    asm volatile("cp.async.cg.shared.global [%0], [%1], 16;"
                 :: "r"(dst), "l"(src) : "memory");
}

// ---------------- prep: split x into fp16 hi/lo ------------------------------
__global__ __launch_bounds__(256) void split_x(const float* __restrict__ x)
{
    const size_t i = (size_t)blockIdx.x * 256 + threadIdx.x;
    const float v = x[i];
    const __half hi = __float2half_rn(v);
    g_xhi[i] = hi;
    g_xlo[i] = __float2half_rn(v - __half2float(hi));
}

// ---------------- prep: Wi -> fp16 -------------------------------------------
__global__ __launch_bounds__(256) void split_wi(const float* __restrict__ Wi)
{
    const size_t i = (size_t)blockIdx.x * 256 + threadIdx.x;
    g_wih[i] = __float2half_rn(Wi[i]);
}

// ---------------- xi = x @ Wi + bi  via mma.sync fp16 2-term -----------------
// (unchanged, validated at rel_err 2.34e-4)
__global__ __launch_bounds__(256, 2) void xi_mma(
    const float* __restrict__ bi, float* __restrict__ xi)
{
    extern __shared__ char sm[];
    const uint32_t su = (uint32_t)__cvta_generic_to_shared(sm);

    const int tid  = threadIdx.x;
    const int wid  = tid >> 5;
    const int lane = tid & 31;
    const int t    = blockIdx.y;
    const int n0   = blockIdx.x * 64;
    const int wm   = wid >> 1;
    const int wn   = wid & 1;

    float acc[2][4][4];
#pragma unroll
    for (int i = 0; i < 2; i++)
#pragma unroll
        for (int j = 0; j < 4; j++)
#pragma unroll
            for (int p = 0; p < 4; p++) acc[i][j][p] = 0.f;

    {
        const uint32_t ab = su + XA_OFF;
#pragma unroll
        for (int it = 0; it < 8; it++) {
            const int idx = tid + it * 256;
            const int term = idx >> 10;
            const int r = (idx >> 3) & 127;
            const int off = idx & 7;
            const __half* src = term ? g_xlo : g_xhi;
            cp16(ab + term * XA_TSZ + r * 144 + off * 16,
                 &src[((size_t)r * 512 + t) * 512 + off * 8]);
        }
#pragma unroll
        for (int it = 0; it < 2; it++) {
            const int idx = tid + it * 256;
            const int r = idx >> 3, off = idx & 7;
            cp16(su + XB_OFF + r * 144 + off * 16,
                 &g_wih[(size_t)r * 3072 + n0 + off * 8]);
        }
        asm volatile("cp.async.commit_group;" ::: "memory");
    }

#pragma unroll 1
    for (int c = 0; c < 8; c++) {
        asm volatile("cp.async.wait_group 0;" ::: "memory");
        __syncthreads();

        if (c < 7) {
            const int nb = (c + 1) & 1;
            const int kb = (c + 1) * 64;
            const uint32_t ab = su + XA_OFF + nb * XA_BUFSZ;
#pragma unroll
            for (int it = 0; it < 8; it++) {
                const int idx = tid + it * 256;
                const int term = idx >> 10;
                const int r = (idx >> 3) & 127;
                const int off = idx & 7;
                const __half* src = term ? g_xlo : g_xhi;
                cp16(ab + term * XA_TSZ + r * 144 + off * 16,
                     &src[((size_t)r * 512 + t) * 512 + kb + off * 8]);
            }
#pragma unroll
            for (int it = 0; it < 2; it++) {
                const int idx = tid + it * 256;
                const int r = idx >> 3, off = idx & 7;
                cp16(su + XB_OFF + nb * XB_BUFSZ + r * 144 + off * 16,
                     &g_wih[(size_t)(kb + r) * 3072 + n0 + off * 8]);
            }
            asm volatile("cp.async.commit_group;" ::: "memory");
        }

        const uint32_t abuf = su + XA_OFF + (c & 1) * XA_BUFSZ;
        const uint32_t bbuf = su + XB_OFF + (c & 1) * XB_BUFSZ;
#pragma unroll
        for (int kk = 0; kk < 4; kk++) {
            uint32_t a_hi[2][4], a_lo[2][4];
#pragma unroll
            for (int tile = 0; tile < 2; tile++) {
                const uint32_t aaddr = abuf
                    + (wm * 32 + tile * 16 + (lane & 15)) * 144
                    + (lane >> 4) * 16 + kk * 32;
                ldmatrix_x4(a_hi[tile], aaddr);
                ldmatrix_x4(a_lo[tile], aaddr + XA_TSZ);
            }
            uint32_t bf[4][2];
#pragma unroll
            for (int nt = 0; nt < 4; nt++) {
                const uint32_t baddr = bbuf
                    + (kk * 16 + (lane & 15)) * 144
                    + (wn * 32 + nt * 8) * 2;
                ldmatrix_x2t(bf[nt][0], bf[nt][1], baddr);
            }
#pragma unroll
            for (int tile = 0; tile < 2; tile++)
#pragma unroll
                for (int nt = 0; nt < 4; nt++) {
                    mma_f16(acc[tile][nt], a_hi[tile], bf[nt][0], bf[nt][1]);
                    mma_f16(acc[tile][nt], a_lo[tile], bf[nt][0], bf[nt][1]);
                }
        }
    }

    const int grp = lane >> 2;
    const int nlo = (lane & 3) * 2;
#pragma unroll
    for (int nt = 0; nt < 4; nt++) {
        const int n = n0 + wn * 32 + nt * 8 + nlo;
        const float2 bv = *reinterpret_cast<const float2*>(&bi[n]);
#pragma unroll
        for (int tile = 0; tile < 2; tile++) {
#pragma unroll
            for (int half = 0; half < 2; half++) {
                const int b = wm * 32 + tile * 16 + grp + half * 8;
                float2 o;
                o.x = acc[tile][nt][half * 2 + 0] + bv.x;
                o.y = acc[tile][nt][half * 2 + 1] + bv.y;
                *reinterpret_cast<float2*>(
                    &xi[((size_t)t * 128 + b) * 3072 + n]) = o;
            }
        }
    }
}

// ---------------- init: zero h buffer 0 + reset barrier ---------------------
__global__ void init_state()
{
    const int idx = blockIdx.x * 256 + threadIdx.x;   // < 131072
    g_hf[0][idx] = __float2half(0.f);
    if (idx == 0) { g_bar_count = 0; g_bar_sense = 0; }
}

// ---------------- grid barrier ----------------------------------------------
__device__ __forceinline__ void grid_barrier(unsigned& sense)
{
    __syncthreads();
    if (threadIdx.x == 0) {
        const unsigned s = sense + 1;
        __threadfence();
        if (atomicAdd(&g_bar_count, 1u) == gridDim.x - 1) {
            atomicExch(&g_bar_count, 0u);
            __threadfence();
            g_bar_sense = s;
        } else {
            while (g_bar_sense != s) { __nanosleep(32); }
        }
        __threadfence();
        sense = s;
    }
    __syncthreads();
}

// ---------------- persistent mma.sync GRU recurrence (fp16 1-term W) --------
// Round-7 structure (measured fastest): 128 CTAs x 256 threads (8 warps),
// CTA owns j-slice j0 = bid*8 (3 gates, N=24), warp w owns batch rows
// [w*16, w*16+16), warp-private 3-stage cp.async A staging (__syncwarp only).
// Change vs R7: W stored as SINGLE fp16 term -> mma count halves (192/warp).
__global__ __launch_bounds__(256, 1)
void gru_mma_persist(const float* __restrict__ Wh, const float* __restrict__ bh,
                     float* __restrict__ out)
{
    extern __shared__ char sm[];
    const uint32_t smem_u32 = (uint32_t)__cvta_generic_to_shared(sm);
    uint32_t* const ws = reinterpret_cast<uint32_t*>(sm + WS_OFF);

    const int tid  = threadIdx.x;
    const int wid  = tid >> 5;
    const int lane = tid & 31;
    const int bid  = blockIdx.x;
    const int j0   = bid * 8;

    // one-time: format Wh slice into fp16 mma B fragments (single term)
    for (int idx = tid; idx < 12288; idx += 256) {
        const int r    = idx & 1;
        const int l    = (idx >> 1) & 31;
        const int rest = idx >> 6;
        const int tt   = rest % 3;
        const int ks   = rest / 3;          // 0..63
        const int n = tt * 1024 + j0 + (l >> 2);
        const int k = ks * 16 + r * 8 + (l & 3) * 2;

        const __half e0 = __float2half_rn(Wh[(size_t)k * 3072 + n]);
        const __half e1 = __float2half_rn(Wh[(size_t)(k + 1) * 3072 + n]);
        ws[idx] = ((uint32_t)__half_as_ushort(e1) << 16)
                |  (uint32_t)__half_as_ushort(e0);
    }
    __syncthreads();

    const int b0 = wid * 16 + (lane >> 2);
    const int jb = j0 + (lane & 3) * 2;

    float bhv[3][2];
#pragma unroll
    for (int g = 0; g < 3; g++) {
        bhv[g][0] = bh[g * 1024 + jb];
        bhv[g][1] = bh[g * 1024 + jb + 1];
    }

    float hp[4];
#pragma unroll
    for (int p = 0; p < 4; p++) hp[p] = 0.f;

    // warp-private A staging base
    const uint32_t awarp = smem_u32 + A_OFF + wid * A_WARP_SZ;
    const int arow = wid * 16;    // this warp's first batch row

    unsigned sense = 0;

#pragma unroll 1
    for (int t = 0; t < TSTEPS; t++) {
        const float* __restrict__ xi_t = g_xi + (size_t)t * 128 * 3072;
        const __half* __restrict__ hs = g_hf[t & 1];
        __half* __restrict__ hd = g_hf[(t + 1) & 1];

        // xi prefetch into registers (overlaps with staging/mma)
        float xiv[3][2][2];
#pragma unroll
        for (int g = 0; g < 3; g++)
#pragma unroll
            for (int rr = 0; rr < 2; rr++) {
                const float2 v = *reinterpret_cast<const float2*>(
                    &xi_t[(size_t)(b0 + rr * 8) * 3072 + g * 1024 + jb]);
                xiv[g][rr][0] = v.x; xiv[g][rr][1] = v.y;
            }

        float acc[3][4];
#pragma unroll
        for (int g = 0; g < 3; g++)
#pragma unroll
            for (int p = 0; p < 4; p++) acc[g][p] = 0.f;

        // prologue: stage chunks 0 and 1 (k-chunk = 128)
#pragma unroll
        for (int pc = 0; pc < 2; pc++) {
            const uint32_t ab = awarp + pc * A_BUF_SZ;
#pragma unroll
            for (int it = 0; it < 8; it++) {
                const int idx = lane + it * 32;          // 0..255
                const int row = idx >> 4, off = idx & 15;
                cp16(ab + row * 272 + off * 16,
                     &hs[(arow + row) * 1024 + pc * 128 + off * 8]);
            }
            asm volatile("cp.async.commit_group;" ::: "memory");
        }

#pragma unroll 1
        for (int c = 0; c < 8; c++) {
            if (c < 6)
                asm volatile("cp.async.wait_group 1;" ::: "memory");
            else
                asm volatile("cp.async.wait_group 0;" ::: "memory");
            __syncwarp();

            const uint32_t abuf = awarp + (c % 3) * A_BUF_SZ;
#pragma unroll
            for (int kk = 0; kk < 8; kk++) {
                uint32_t a[4];
                ldmatrix_x4(a, abuf + (lane & 15) * 272
                               + (lane >> 4) * 16 + kk * 32);
                const int ks = c * 8 + kk;
#pragma unroll
                for (int tt = 0; tt < 3; tt++) {
                    const uint32_t boff = smem_u32 + WS_OFF
                                        + (uint32_t)((ks * 3 + tt) * 256) + lane * 8;
                    uint32_t bh0, bh1;
                    asm("ld.shared.v2.u32 {%0,%1}, [%2];"
                        : "=r"(bh0), "=r"(bh1) : "r"(boff));
                    mma_f16(acc[tt], a, bh0, bh1);
                }
            }

            if (c < 6) {   // stage chunk c+2
                const uint32_t ab = awarp + ((c + 2) % 3) * A_BUF_SZ;
                const int kb = (c + 2) * 128;
#pragma unroll
                for (int it = 0; it < 8; it++) {
                    const int idx = lane + it * 32;
                    const int row = idx >> 4, off = idx & 15;
                    cp16(ab + row * 272 + off * 16,
                         &hs[(arow + row) * 1024 + kb + off * 8]);
                }
                asm volatile("cp.async.commit_group;" ::: "memory");
            }
        }

        // ---------------- gate epilogue (registers only) ----------------
#pragma unroll
        for (int rr = 0; rr < 2; rr++) {
            const int b = b0 + rr * 8;
            float hy2[2];
#pragma unroll
            for (int q = 0; q < 2; q++) {
                const int p = rr * 2 + q;
                const float hr = acc[0][p] + bhv[0][q];
                const float hz = acc[1][p] + bhv[1][q];
                const float hn = acc[2][p] + bhv[2][q];
                const float rg = 1.f / (1.f + expf(-(xiv[0][rr][q] + hr)));
                const float zg = 1.f / (1.f + expf(-(xiv[1][rr][q] + hz)));
                const float ng = tanhf(xiv[2][rr][q] + rg * hn);
                const float hy = zg * ng + (1.f - zg) * hp[p];
                hp[p] = hy;
                hy2[q] = hy;
            }
            const __half e0 = __float2half_rn(hy2[0]);
            const __half e1 = __float2half_rn(hy2[1]);
            *reinterpret_cast<uint32_t*>(&hd[b * 1024 + jb]) =
                ((uint32_t)__half_as_ushort(e1) << 16)
                | (uint32_t)__half_as_ushort(e0);
            if (t == TSTEPS - 1) {
                float2 o; o.x = hy2[0]; o.y = hy2[1];
                *reinterpret_cast<float2*>(&out[b * 1024 + jb]) = o;
            }
        }

        if (t != TSTEPS - 1) grid_barrier(sense);
    }
}

// ---------------- launch ----------------------------------------------------
extern "C" void kernel_launch(void* const* d_in, const int* in_sizes, int n_in,
                              void* d_out, int out_size)
{
    const float* x  = (const float*)d_in[0];
    const float* Wi = (const float*)d_in[1];
    const float* bi = (const float*)d_in[2];
    const float* Wh = (const float*)d_in[3];
    const float* bh = (const float*)d_in[4];
    float* out = (float*)d_out;

    float* xi_ptr;
    cudaGetSymbolAddress((void**)&xi_ptr, g_xi);

    cudaFuncSetAttribute(gru_mma_persist,
                         cudaFuncAttributeMaxDynamicSharedMemorySize, SMEM_TOTAL);
    cudaFuncSetAttribute(xi_mma,
                         cudaFuncAttributeMaxDynamicSharedMemorySize, SMEM_XI);

    // prep: fp16 splits
    split_x<<<131072, 256>>>(x);
    split_wi<<<6144, 256>>>(Wi);
    // xi = x @ Wi + bi on tensor cores (fp16 2-term)
    xi_mma<<<dim3(48, 512), 256, SMEM_XI>>>(bi, xi_ptr);
    // zero h buffer + barrier
    init_state<<<512, 256>>>();
    // whole 512-step recurrence on tensor cores (fp16 single-term W)
    gru_mma_persist<<<NC, 256, SMEM_TOTAL>>>(Wh, bh, out);
}

// round 10
// speedup vs baseline: 1.4063x; 1.0884x over previous
#include <cuda_runtime.h>
#include <cuda_bf16.h>
#include <cuda_fp16.h>
#include <math.h>
#include <stdint.h>

#define NC      128       // persistent CTAs; CTA owns hidden slice j0 = bid*8
#define TSTEPS  512

// ---------------- scratch (__device__ globals; no runtime allocation) ------
__device__ float g_xi[(size_t)512 * 128 * 3072];     // [T][B][3H]
__device__ __half g_xh[(size_t)128 * 512 * 512];     // x fp16
__device__ __half g_wih[(size_t)512 * 3072];         // Wi fp16
__device__ __half g_hf[2][128 * 1024];               // h fp16 (ping-pong)
__device__ unsigned g_bar_count;
__device__ volatile unsigned g_bar_sense;

// ---------------- recurrence SMEM layout (dynamic, bytes) -------------------
// ws: W fragments fp16 (single term): [ks64][gate3][lane32][reg2] u32 = 48KB
// A staging: per-warp private, 3 bufs x (16 rows x 272B) = 13056 B/warp
#define WS_OFF     0
#define A_OFF      49152
#define A_BUF_SZ   4352          // 16 rows * 272B
#define A_WARP_SZ  13056         // 3 bufs
#define SMEM_TOTAL (49152 + 8 * 13056)   // 153600

// ---------------- xi mma SMEM layout (bytes) --------------------------------
// A: [buf2][128 rows][72 fp16] ; B: [buf2][64 rows][72 fp16]
#define XA_OFF   0
#define XA_BUFSZ 18432           // 128*144
#define XB_OFF   36864
#define XB_BUFSZ 9216            // 64*144
#define SMEM_XI  55296

// ---------------- PTX helpers ------------------------------------------------
__device__ __forceinline__ void mma_f16(float* c, const uint32_t* a,
                                        uint32_t b0, uint32_t b1) {
    asm volatile(
        "mma.sync.aligned.m16n8k16.row.col.f32.f16.f16.f32 "
        "{%0,%1,%2,%3}, {%4,%5,%6,%7}, {%8,%9}, {%0,%1,%2,%3};"
        : "+f"(c[0]), "+f"(c[1]), "+f"(c[2]), "+f"(c[3])
        : "r"(a[0]), "r"(a[1]), "r"(a[2]), "r"(a[3]), "r"(b0), "r"(b1));
}

__device__ __forceinline__ void ldmatrix_x4(uint32_t* a, uint32_t addr) {
    asm volatile(
        "ldmatrix.sync.aligned.m8n8.x4.shared.b16 {%0,%1,%2,%3}, [%4];"
        : "=r"(a[0]), "=r"(a[1]), "=r"(a[2]), "=r"(a[3]) : "r"(addr));
}

__device__ __forceinline__ void ldmatrix_x2t(uint32_t& b0, uint32_t& b1,
                                             uint32_t addr) {
    asm volatile(
        "ldmatrix.sync.aligned.m8n8.x2.trans.shared.b16 {%0,%1}, [%2];"
        : "=r"(b0), "=r"(b1) : "r"(addr));
}

__device__ __forceinline__ void cp16(uint32_t dst, const void* src) {
    asm volatile("cp.async.cg.shared.global [%0], [%1], 16;"
                 :: "r"(dst), "l"(src) : "memory");
}

// ---------------- prep: x -> fp16 --------------------------------------------
__global__ __launch_bounds__(256) void split_x(const float* __restrict__ x)
{
    const size_t i = (size_t)blockIdx.x * 256 + threadIdx.x;
    g_xh[i] = __float2half_rn(x[i]);
}

// ---------------- prep: Wi -> fp16 -------------------------------------------
__global__ __launch_bounds__(256) void split_wi(const float* __restrict__ Wi)
{
    const size_t i = (size_t)blockIdx.x * 256 + threadIdx.x;
    g_wih[i] = __float2half_rn(Wi[i]);
}

// ---------------- xi = x @ Wi + bi  via mma.sync fp16 single-term ------------
// grid (48, 512): blockIdx.y = t, blockIdx.x = 64-wide n-slice.
// 8 warps as 4(m) x 2(n); warp tile 32m x 32n. K = 512 in 8 chunks of 64.
__global__ __launch_bounds__(256, 2) void xi_mma(
    const float* __restrict__ bi, float* __restrict__ xi)
{
    extern __shared__ char sm[];
    const uint32_t su = (uint32_t)__cvta_generic_to_shared(sm);

    const int tid  = threadIdx.x;
    const int wid  = tid >> 5;
    const int lane = tid & 31;
    const int t    = blockIdx.y;
    const int n0   = blockIdx.x * 64;
    const int wm   = wid >> 1;
    const int wn   = wid & 1;

    float acc[2][4][4];
#pragma unroll
    for (int i = 0; i < 2; i++)
#pragma unroll
        for (int j = 0; j < 4; j++)
#pragma unroll
            for (int p = 0; p < 4; p++) acc[i][j][p] = 0.f;

    {
        const uint32_t ab = su + XA_OFF;
#pragma unroll
        for (int it = 0; it < 4; it++) {
            const int idx = tid + it * 256;          // 0..1023
            const int r = idx >> 3, off = idx & 7;
            cp16(ab + r * 144 + off * 16,
                 &g_xh[((size_t)r * 512 + t) * 512 + off * 8]);
        }
#pragma unroll
        for (int it = 0; it < 2; it++) {
            const int idx = tid + it * 256;          // 0..511
            const int r = idx >> 3, off = idx & 7;
            cp16(su + XB_OFF + r * 144 + off * 16,
                 &g_wih[(size_t)r * 3072 + n0 + off * 8]);
        }
        asm volatile("cp.async.commit_group;" ::: "memory");
    }

#pragma unroll 1
    for (int c = 0; c < 8; c++) {
        asm volatile("cp.async.wait_group 0;" ::: "memory");
        __syncthreads();

        if (c < 7) {
            const int nb = (c + 1) & 1;
            const int kb = (c + 1) * 64;
            const uint32_t ab = su + XA_OFF + nb * XA_BUFSZ;
#pragma unroll
            for (int it = 0; it < 4; it++) {
                const int idx = tid + it * 256;
                const int r = idx >> 3, off = idx & 7;
                cp16(ab + r * 144 + off * 16,
                     &g_xh[((size_t)r * 512 + t) * 512 + kb + off * 8]);
            }
#pragma unroll
            for (int it = 0; it < 2; it++) {
                const int idx = tid + it * 256;
                const int r = idx >> 3, off = idx & 7;
                cp16(su + XB_OFF + nb * XB_BUFSZ + r * 144 + off * 16,
                     &g_wih[(size_t)(kb + r) * 3072 + n0 + off * 8]);
            }
            asm volatile("cp.async.commit_group;" ::: "memory");
        }

        const uint32_t abuf = su + XA_OFF + (c & 1) * XA_BUFSZ;
        const uint32_t bbuf = su + XB_OFF + (c & 1) * XB_BUFSZ;
#pragma unroll
        for (int kk = 0; kk < 4; kk++) {
            uint32_t a[2][4];
#pragma unroll
            for (int tile = 0; tile < 2; tile++) {
                const uint32_t aaddr = abuf
                    + (wm * 32 + tile * 16 + (lane & 15)) * 144
                    + (lane >> 4) * 16 + kk * 32;
                ldmatrix_x4(a[tile], aaddr);
            }
            uint32_t bf[4][2];
#pragma unroll
            for (int nt = 0; nt < 4; nt++) {
                const uint32_t baddr = bbuf
                    + (kk * 16 + (lane & 15)) * 144
                    + (wn * 32 + nt * 8) * 2;
                ldmatrix_x2t(bf[nt][0], bf[nt][1], baddr);
            }
#pragma unroll
            for (int tile = 0; tile < 2; tile++)
#pragma unroll
                for (int nt = 0; nt < 4; nt++)
                    mma_f16(acc[tile][nt], a[tile], bf[nt][0], bf[nt][1]);
        }
    }

    const int grp = lane >> 2;
    const int nlo = (lane & 3) * 2;
#pragma unroll
    for (int nt = 0; nt < 4; nt++) {
        const int n = n0 + wn * 32 + nt * 8 + nlo;
        const float2 bv = *reinterpret_cast<const float2*>(&bi[n]);
#pragma unroll
        for (int tile = 0; tile < 2; tile++) {
#pragma unroll
            for (int half = 0; half < 2; half++) {
                const int b = wm * 32 + tile * 16 + grp + half * 8;
                float2 o;
                o.x = acc[tile][nt][half * 2 + 0] + bv.x;
                o.y = acc[tile][nt][half * 2 + 1] + bv.y;
                *reinterpret_cast<float2*>(
                    &xi[((size_t)t * 128 + b) * 3072 + n]) = o;
            }
        }
    }
}

// ---------------- init: zero h buffer 0 + reset barrier ---------------------
__global__ void init_state()
{
    const int idx = blockIdx.x * 256 + threadIdx.x;   // < 131072
    g_hf[0][idx] = __float2half(0.f);
    if (idx == 0) { g_bar_count = 0; g_bar_sense = 0; }
}

// ---------------- grid barrier ----------------------------------------------
__device__ __forceinline__ void grid_barrier(unsigned& sense)
{
    __syncthreads();
    if (threadIdx.x == 0) {
        const unsigned s = sense + 1;
        __threadfence();
        if (atomicAdd(&g_bar_count, 1u) == gridDim.x - 1) {
            atomicExch(&g_bar_count, 0u);
            __threadfence();
            g_bar_sense = s;
        } else {
            while (g_bar_sense != s) { __nanosleep(32); }
        }
        __threadfence();
        sense = s;
    }
    __syncthreads();
}

// ---------------- persistent mma.sync GRU recurrence (fp16 1-term W) --------
// (unchanged from round-9 passing kernel — validated fastest)
__global__ __launch_bounds__(256, 1)
void gru_mma_persist(const float* __restrict__ Wh, const float* __restrict__ bh,
                     float* __restrict__ out)
{
    extern __shared__ char sm[];
    const uint32_t smem_u32 = (uint32_t)__cvta_generic_to_shared(sm);
    uint32_t* const ws = reinterpret_cast<uint32_t*>(sm + WS_OFF);

    const int tid  = threadIdx.x;
    const int wid  = tid >> 5;
    const int lane = tid & 31;
    const int bid  = blockIdx.x;
    const int j0   = bid * 8;

    // one-time: format Wh slice into fp16 mma B fragments (single term)
    for (int idx = tid; idx < 12288; idx += 256) {
        const int r    = idx & 1;
        const int l    = (idx >> 1) & 31;
        const int rest = idx >> 6;
        const int tt   = rest % 3;
        const int ks   = rest / 3;          // 0..63
        const int n = tt * 1024 + j0 + (l >> 2);
        const int k = ks * 16 + r * 8 + (l & 3) * 2;

        const __half e0 = __float2half_rn(Wh[(size_t)k * 3072 + n]);
        const __half e1 = __float2half_rn(Wh[(size_t)(k + 1) * 3072 + n]);
        ws[idx] = ((uint32_t)__half_as_ushort(e1) << 16)
                |  (uint32_t)__half_as_ushort(e0);
    }
    __syncthreads();

    const int b0 = wid * 16 + (lane >> 2);
    const int jb = j0 + (lane & 3) * 2;

    float bhv[3][2];
#pragma unroll
    for (int g = 0; g < 3; g++) {
        bhv[g][0] = bh[g * 1024 + jb];
        bhv[g][1] = bh[g * 1024 + jb + 1];
    }

    float hp[4];
#pragma unroll
    for (int p = 0; p < 4; p++) hp[p] = 0.f;

    const uint32_t awarp = smem_u32 + A_OFF + wid * A_WARP_SZ;
    const int arow = wid * 16;

    unsigned sense = 0;

#pragma unroll 1
    for (int t = 0; t < TSTEPS; t++) {
        const float* __restrict__ xi_t = g_xi + (size_t)t * 128 * 3072;
        const __half* __restrict__ hs = g_hf[t & 1];
        __half* __restrict__ hd = g_hf[(t + 1) & 1];

        float xiv[3][2][2];
#pragma unroll
        for (int g = 0; g < 3; g++)
#pragma unroll
            for (int rr = 0; rr < 2; rr++) {
                const float2 v = *reinterpret_cast<const float2*>(
                    &xi_t[(size_t)(b0 + rr * 8) * 3072 + g * 1024 + jb]);
                xiv[g][rr][0] = v.x; xiv[g][rr][1] = v.y;
            }

        float acc[3][4];
#pragma unroll
        for (int g = 0; g < 3; g++)
#pragma unroll
            for (int p = 0; p < 4; p++) acc[g][p] = 0.f;

#pragma unroll
        for (int pc = 0; pc < 2; pc++) {
            const uint32_t ab = awarp + pc * A_BUF_SZ;
#pragma unroll
            for (int it = 0; it < 8; it++) {
                const int idx = lane + it * 32;
                const int row = idx >> 4, off = idx & 15;
                cp16(ab + row * 272 + off * 16,
                     &hs[(arow + row) * 1024 + pc * 128 + off * 8]);
            }
            asm volatile("cp.async.commit_group;" ::: "memory");
        }

#pragma unroll 1
        for (int c = 0; c < 8; c++) {
            if (c < 6)
                asm volatile("cp.async.wait_group 1;" ::: "memory");
            else
                asm volatile("cp.async.wait_group 0;" ::: "memory");
            __syncwarp();

            const uint32_t abuf = awarp + (c % 3) * A_BUF_SZ;
#pragma unroll
            for (int kk = 0; kk < 8; kk++) {
                uint32_t a[4];
                ldmatrix_x4(a, abuf + (lane & 15) * 272
                               + (lane >> 4) * 16 + kk * 32);
                const int ks = c * 8 + kk;
#pragma unroll
                for (int tt = 0; tt < 3; tt++) {
                    const uint32_t boff = smem_u32 + WS_OFF
                                        + (uint32_t)((ks * 3 + tt) * 256) + lane * 8;
                    uint32_t bh0, bh1;
                    asm("ld.shared.v2.u32 {%0,%1}, [%2];"
                        : "=r"(bh0), "=r"(bh1) : "r"(boff));
                    mma_f16(acc[tt], a, bh0, bh1);
                }
            }

            if (c < 6) {
                const uint32_t ab = awarp + ((c + 2) % 3) * A_BUF_SZ;
                const int kb = (c + 2) * 128;
#pragma unroll
                for (int it = 0; it < 8; it++) {
                    const int idx = lane + it * 32;
                    const int row = idx >> 4, off = idx & 15;
                    cp16(ab + row * 272 + off * 16,
                         &hs[(arow + row) * 1024 + kb + off * 8]);
                }
                asm volatile("cp.async.commit_group;" ::: "memory");
            }
        }

#pragma unroll
        for (int rr = 0; rr < 2; rr++) {
            const int b = b0 + rr * 8;
            float hy2[2];
#pragma unroll
            for (int q = 0; q < 2; q++) {
                const int p = rr * 2 + q;
                const float hr = acc[0][p] + bhv[0][q];
                const float hz = acc[1][p] + bhv[1][q];
                const float hn = acc[2][p] + bhv[2][q];
                const float rg = 1.f / (1.f + expf(-(xiv[0][rr][q] + hr)));
                const float zg = 1.f / (1.f + expf(-(xiv[1][rr][q] + hz)));
                const float ng = tanhf(xiv[2][rr][q] + rg * hn);
                const float hy = zg * ng + (1.f - zg) * hp[p];
                hp[p] = hy;
                hy2[q] = hy;
            }
            const __half e0 = __float2half_rn(hy2[0]);
            const __half e1 = __float2half_rn(hy2[1]);
            *reinterpret_cast<uint32_t*>(&hd[b * 1024 + jb]) =
                ((uint32_t)__half_as_ushort(e1) << 16)
                | (uint32_t)__half_as_ushort(e0);
            if (t == TSTEPS - 1) {
                float2 o; o.x = hy2[0]; o.y = hy2[1];
                *reinterpret_cast<float2*>(&out[b * 1024 + jb]) = o;
            }
        }

        if (t != TSTEPS - 1) grid_barrier(sense);
    }
}

// ---------------- launch ----------------------------------------------------
extern "C" void kernel_launch(void* const* d_in, const int* in_sizes, int n_in,
                              void* d_out, int out_size)
{
    const float* x  = (const float*)d_in[0];
    const float* Wi = (const float*)d_in[1];
    const float* bi = (const float*)d_in[2];
    const float* Wh = (const float*)d_in[3];
    const float* bh = (const float*)d_in[4];
    float* out = (float*)d_out;

    float* xi_ptr;
    cudaGetSymbolAddress((void**)&xi_ptr, g_xi);

    cudaFuncSetAttribute(gru_mma_persist,
                         cudaFuncAttributeMaxDynamicSharedMemorySize, SMEM_TOTAL);
    cudaFuncSetAttribute(xi_mma,
                         cudaFuncAttributeMaxDynamicSharedMemorySize, SMEM_XI);

    // prep: fp16 conversions
    split_x<<<131072, 256>>>(x);
    split_wi<<<6144, 256>>>(Wi);
    // xi = x @ Wi + bi on tensor cores (fp16 single-term)
    xi_mma<<<dim3(48, 512), 256, SMEM_XI>>>(bi, xi_ptr);
    // zero h buffer + barrier
    init_state<<<512, 256>>>();
    // whole 512-step recurrence on tensor cores (fp16 single-term W)
    gru_mma_persist<<<NC, 256, SMEM_TOTAL>>>(Wh, bh, out);
}

// round 11
// speedup vs baseline: 1.5373x; 1.0932x over previous
#include <cuda_runtime.h>
#include <cuda_bf16.h>
#include <cuda_fp16.h>
#include <math.h>
#include <stdint.h>

#define NC      128       // persistent CTAs; CTA owns hidden slice j0 = bid*8
#define TSTEPS  512

// ---------------- scratch (__device__ globals; no runtime allocation) ------
__device__ float g_xi[(size_t)512 * 128 * 3072];     // [T][B][3H]
__device__ __half g_xh[(size_t)128 * 512 * 512];     // x fp16
__device__ __half g_wih[(size_t)512 * 3072];         // Wi fp16
__device__ __half g_hf[2][128 * 1024];               // h fp16 (ping-pong)
__device__ unsigned g_bar_count;                     // monotone step counter

// ---------------- recurrence SMEM layout (dynamic, bytes) -------------------
#define WS_OFF     0
#define A_OFF      49152
#define A_BUF_SZ   4352          // 16 rows * 272B
#define A_WARP_SZ  13056         // 3 bufs
#define SMEM_TOTAL (49152 + 8 * 13056)   // 153600

// ---------------- xi mma SMEM layout (bytes) --------------------------------
#define XA_OFF   0
#define XA_BUFSZ 18432           // 128*144
#define XB_OFF   36864
#define XB_BUFSZ 9216            // 64*144
#define SMEM_XI  55296

// ---------------- PTX helpers ------------------------------------------------
__device__ __forceinline__ void mma_f16(float* c, const uint32_t* a,
                                        uint32_t b0, uint32_t b1) {
    asm volatile(
        "mma.sync.aligned.m16n8k16.row.col.f32.f16.f16.f32 "
        "{%0,%1,%2,%3}, {%4,%5,%6,%7}, {%8,%9}, {%0,%1,%2,%3};"
        : "+f"(c[0]), "+f"(c[1]), "+f"(c[2]), "+f"(c[3])
        : "r"(a[0]), "r"(a[1]), "r"(a[2]), "r"(a[3]), "r"(b0), "r"(b1));
}

__device__ __forceinline__ void ldmatrix_x4(uint32_t* a, uint32_t addr) {
    asm volatile(
        "ldmatrix.sync.aligned.m8n8.x4.shared.b16 {%0,%1,%2,%3}, [%4];"
        : "=r"(a[0]), "=r"(a[1]), "=r"(a[2]), "=r"(a[3]) : "r"(addr));
}

__device__ __forceinline__ void ldmatrix_x2t(uint32_t& b0, uint32_t& b1,
                                             uint32_t addr) {
    asm volatile(
        "ldmatrix.sync.aligned.m8n8.x2.trans.shared.b16 {%0,%1}, [%2];"
        : "=r"(b0), "=r"(b1) : "r"(addr));
}

__device__ __forceinline__ void cp16(uint32_t dst, const void* src) {
    asm volatile("cp.async.cg.shared.global [%0], [%1], 16;"
                 :: "r"(dst), "l"(src) : "memory");
}

// ---------------- prep: x -> fp16 --------------------------------------------
__global__ __launch_bounds__(256) void split_x(const float* __restrict__ x)
{
    const size_t i = (size_t)blockIdx.x * 256 + threadIdx.x;
    g_xh[i] = __float2half_rn(x[i]);
}

// ---------------- prep: Wi -> fp16 -------------------------------------------
__global__ __launch_bounds__(256) void split_wi(const float* __restrict__ Wi)
{
    const size_t i = (size_t)blockIdx.x * 256 + threadIdx.x;
    g_wih[i] = __float2half_rn(Wi[i]);
}

// ---------------- xi = x @ Wi + bi  via mma.sync fp16 single-term ------------
// grid (48, 512): blockIdx.y = t, blockIdx.x = 64-wide n-slice.
// 8 warps as 4(m) x 2(n); warp tile 32m x 32n. K = 512 in 8 chunks of 64.
// 3 CTAs/SM co-residency (smem 55KB, regs <= 85) to hide per-CTA bubbles.
__global__ __launch_bounds__(256, 3) void xi_mma(
    const float* __restrict__ bi, float* __restrict__ xi)
{
    extern __shared__ char sm[];
    const uint32_t su = (uint32_t)__cvta_generic_to_shared(sm);

    const int tid  = threadIdx.x;
    const int wid  = tid >> 5;
    const int lane = tid & 31;
    const int t    = blockIdx.y;
    const int n0   = blockIdx.x * 64;
    const int wm   = wid >> 1;
    const int wn   = wid & 1;

    float acc[2][4][4];
#pragma unroll
    for (int i = 0; i < 2; i++)
#pragma unroll
        for (int j = 0; j < 4; j++)
#pragma unroll
            for (int p = 0; p < 4; p++) acc[i][j][p] = 0.f;

    {
        const uint32_t ab = su + XA_OFF;
#pragma unroll
        for (int it = 0; it < 4; it++) {
            const int idx = tid + it * 256;          // 0..1023
            const int r = idx >> 3, off = idx & 7;
            cp16(ab + r * 144 + off * 16,
                 &g_xh[((size_t)r * 512 + t) * 512 + off * 8]);
        }
#pragma unroll
        for (int it = 0; it < 2; it++) {
            const int idx = tid + it * 256;          // 0..511
            const int r = idx >> 3, off = idx & 7;
            cp16(su + XB_OFF + r * 144 + off * 16,
                 &g_wih[(size_t)r * 3072 + n0 + off * 8]);
        }
        asm volatile("cp.async.commit_group;" ::: "memory");
    }

#pragma unroll 1
    for (int c = 0; c < 8; c++) {
        asm volatile("cp.async.wait_group 0;" ::: "memory");
        __syncthreads();

        if (c < 7) {
            const int nb = (c + 1) & 1;
            const int kb = (c + 1) * 64;
            const uint32_t ab = su + XA_OFF + nb * XA_BUFSZ;
#pragma unroll
            for (int it = 0; it < 4; it++) {
                const int idx = tid + it * 256;
                const int r = idx >> 3, off = idx & 7;
                cp16(ab + r * 144 + off * 16,
                     &g_xh[((size_t)r * 512 + t) * 512 + kb + off * 8]);
            }
#pragma unroll
            for (int it = 0; it < 2; it++) {
                const int idx = tid + it * 256;
                const int r = idx >> 3, off = idx & 7;
                cp16(su + XB_OFF + nb * XB_BUFSZ + r * 144 + off * 16,
                     &g_wih[(size_t)(kb + r) * 3072 + n0 + off * 8]);
            }
            asm volatile("cp.async.commit_group;" ::: "memory");
        }

        const uint32_t abuf = su + XA_OFF + (c & 1) * XA_BUFSZ;
        const uint32_t bbuf = su + XB_OFF + (c & 1) * XB_BUFSZ;
#pragma unroll
        for (int kk = 0; kk < 4; kk++) {
            uint32_t a[2][4];
#pragma unroll
            for (int tile = 0; tile < 2; tile++) {
                const uint32_t aaddr = abuf
                    + (wm * 32 + tile * 16 + (lane & 15)) * 144
                    + (lane >> 4) * 16 + kk * 32;
                ldmatrix_x4(a[tile], aaddr);
            }
            uint32_t bf[4][2];
#pragma unroll
            for (int nt = 0; nt < 4; nt++) {
                const uint32_t baddr = bbuf
                    + (kk * 16 + (lane & 15)) * 144
                    + (wn * 32 + nt * 8) * 2;
                ldmatrix_x2t(bf[nt][0], bf[nt][1], baddr);
            }
#pragma unroll
            for (int tile = 0; tile < 2; tile++)
#pragma unroll
                for (int nt = 0; nt < 4; nt++)
                    mma_f16(acc[tile][nt], a[tile], bf[nt][0], bf[nt][1]);
        }
    }

    const int grp = lane >> 2;
    const int nlo = (lane & 3) * 2;
#pragma unroll
    for (int nt = 0; nt < 4; nt++) {
        const int n = n0 + wn * 32 + nt * 8 + nlo;
        const float2 bv = *reinterpret_cast<const float2*>(&bi[n]);
#pragma unroll
        for (int tile = 0; tile < 2; tile++) {
#pragma unroll
            for (int half = 0; half < 2; half++) {
                const int b = wm * 32 + tile * 16 + grp + half * 8;
                float2 o;
                o.x = acc[tile][nt][half * 2 + 0] + bv.x;
                o.y = acc[tile][nt][half * 2 + 1] + bv.y;
                *reinterpret_cast<float2*>(
                    &xi[((size_t)t * 128 + b) * 3072 + n]) = o;
            }
        }
    }
}

// ---------------- init: zero h buffer 0 + reset barrier counter -------------
__global__ void init_state()
{
    const int idx = blockIdx.x * 256 + threadIdx.x;   // < 131072
    g_hf[0][idx] = __float2half(0.f);
    if (idx == 0) g_bar_count = 0;
}

// ---------------- monotone-counter grid barrier ------------------------------
// arrive: red.release (orders this CTA's prior writes);
// wait: relaxed poll for count >= target, then one acq_rel fence.
__device__ __forceinline__ void grid_barrier_step(unsigned target)
{
    __syncthreads();
    if (threadIdx.x == 0) {
        asm volatile("red.release.gpu.global.add.u32 [%0], 1;"
                     :: "l"(&g_bar_count) : "memory");
        unsigned v;
        while (true) {
            asm volatile("ld.relaxed.gpu.global.u32 %0, [%1];"
                         : "=r"(v) : "l"(&g_bar_count) : "memory");
            if (v >= target) break;
            __nanosleep(32);
        }
        asm volatile("fence.acq_rel.gpu;" ::: "memory");
    }
    __syncthreads();
}

// ---------------- persistent mma.sync GRU recurrence (fp16 1-term W) --------
// 128 CTAs x 256 threads (8 warps), CTA owns j-slice j0 = bid*8 (3 gates,
// N=24), warp w owns batch rows [w*16, w*16+16), warp-private 3-stage
// cp.async A staging. One monotone-counter barrier per step.
__global__ __launch_bounds__(256, 1)
void gru_mma_persist(const float* __restrict__ Wh, const float* __restrict__ bh,
                     float* __restrict__ out)
{
    extern __shared__ char sm[];
    const uint32_t smem_u32 = (uint32_t)__cvta_generic_to_shared(sm);
    uint32_t* const ws = reinterpret_cast<uint32_t*>(sm + WS_OFF);

    const int tid  = threadIdx.x;
    const int wid  = tid >> 5;
    const int lane = tid & 31;
    const int bid  = blockIdx.x;
    const int j0   = bid * 8;

    // one-time: format Wh slice into fp16 mma B fragments (single term)
    for (int idx = tid; idx < 12288; idx += 256) {
        const int r    = idx & 1;
        const int l    = (idx >> 1) & 31;
        const int rest = idx >> 6;
        const int tt   = rest % 3;
        const int ks   = rest / 3;          // 0..63
        const int n = tt * 1024 + j0 + (l >> 2);
        const int k = ks * 16 + r * 8 + (l & 3) * 2;

        const __half e0 = __float2half_rn(Wh[(size_t)k * 3072 + n]);
        const __half e1 = __float2half_rn(Wh[(size_t)(k + 1) * 3072 + n]);
        ws[idx] = ((uint32_t)__half_as_ushort(e1) << 16)
                |  (uint32_t)__half_as_ushort(e0);
    }
    __syncthreads();

    const int b0 = wid * 16 + (lane >> 2);
    const int jb = j0 + (lane & 3) * 2;

    float bhv[3][2];
#pragma unroll
    for (int g = 0; g < 3; g++) {
        bhv[g][0] = bh[g * 1024 + jb];
        bhv[g][1] = bh[g * 1024 + jb + 1];
    }

    float hp[4];
#pragma unroll
    for (int p = 0; p < 4; p++) hp[p] = 0.f;

    const uint32_t awarp = smem_u32 + A_OFF + wid * A_WARP_SZ;
    const int arow = wid * 16;

#pragma unroll 1
    for (int t = 0; t < TSTEPS; t++) {
        const float* __restrict__ xi_t = g_xi + (size_t)t * 128 * 3072;
        const __half* __restrict__ hs = g_hf[t & 1];
        __half* __restrict__ hd = g_hf[(t + 1) & 1];

        // prologue FIRST: h loads are on the critical path after barrier
#pragma unroll
        for (int pc = 0; pc < 2; pc++) {
            const uint32_t ab = awarp + pc * A_BUF_SZ;
#pragma unroll
            for (int it = 0; it < 8; it++) {
                const int idx = lane + it * 32;
                const int row = idx >> 4, off = idx & 15;
                cp16(ab + row * 272 + off * 16,
                     &hs[(arow + row) * 1024 + pc * 128 + off * 8]);
            }
            asm volatile("cp.async.commit_group;" ::: "memory");
        }

        // xi prefetch into registers (step-constant; hidden behind mainloop)
        float xiv[3][2][2];
#pragma unroll
        for (int g = 0; g < 3; g++)
#pragma unroll
            for (int rr = 0; rr < 2; rr++) {
                const float2 v = *reinterpret_cast<const float2*>(
                    &xi_t[(size_t)(b0 + rr * 8) * 3072 + g * 1024 + jb]);
                xiv[g][rr][0] = v.x; xiv[g][rr][1] = v.y;
            }

        float acc[3][4];
#pragma unroll
        for (int g = 0; g < 3; g++)
#pragma unroll
            for (int p = 0; p < 4; p++) acc[g][p] = 0.f;

#pragma unroll 1
        for (int c = 0; c < 8; c++) {
            if (c < 6)
                asm volatile("cp.async.wait_group 1;" ::: "memory");
            else
                asm volatile("cp.async.wait_group 0;" ::: "memory");
            __syncwarp();

            const uint32_t abuf = awarp + (c % 3) * A_BUF_SZ;
#pragma unroll
            for (int kk = 0; kk < 8; kk++) {
                uint32_t a[4];
                ldmatrix_x4(a, abuf + (lane & 15) * 272
                               + (lane >> 4) * 16 + kk * 32);
                const int ks = c * 8 + kk;
#pragma unroll
                for (int tt = 0; tt < 3; tt++) {
                    const uint32_t boff = smem_u32 + WS_OFF
                                        + (uint32_t)((ks * 3 + tt) * 256) + lane * 8;
                    uint32_t bh0, bh1;
                    asm("ld.shared.v2.u32 {%0,%1}, [%2];"
                        : "=r"(bh0), "=r"(bh1) : "r"(boff));
                    mma_f16(acc[tt], a, bh0, bh1);
                }
            }

            if (c < 6) {
                const uint32_t ab = awarp + ((c + 2) % 3) * A_BUF_SZ;
                const int kb = (c + 2) * 128;
#pragma unroll
                for (int it = 0; it < 8; it++) {
                    const int idx = lane + it * 32;
                    const int row = idx >> 4, off = idx & 15;
                    cp16(ab + row * 272 + off * 16,
                         &hs[(arow + row) * 1024 + kb + off * 8]);
                }
                asm volatile("cp.async.commit_group;" ::: "memory");
            }
        }

        // ---------------- gate epilogue (registers only) ----------------
#pragma unroll
        for (int rr = 0; rr < 2; rr++) {
            const int b = b0 + rr * 8;
            float hy2[2];
#pragma unroll
            for (int q = 0; q < 2; q++) {
                const int p = rr * 2 + q;
                const float hr = acc[0][p] + bhv[0][q];
                const float hz = acc[1][p] + bhv[1][q];
                const float hn = acc[2][p] + bhv[2][q];
                const float rg = 1.f / (1.f + expf(-(xiv[0][rr][q] + hr)));
                const float zg = 1.f / (1.f + expf(-(xiv[1][rr][q] + hz)));
                const float ng = tanhf(xiv[2][rr][q] + rg * hn);
                const float hy = zg * ng + (1.f - zg) * hp[p];
                hp[p] = hy;
                hy2[q] = hy;
            }
            const __half e0 = __float2half_rn(hy2[0]);
            const __half e1 = __float2half_rn(hy2[1]);
            *reinterpret_cast<uint32_t*>(&hd[b * 1024 + jb]) =
                ((uint32_t)__half_as_ushort(e1) << 16)
                | (uint32_t)__half_as_ushort(e0);
            if (t == TSTEPS - 1) {
                float2 o; o.x = hy2[0]; o.y = hy2[1];
                *reinterpret_cast<float2*>(&out[b * 1024 + jb]) = o;
            }
        }

        if (t != TSTEPS - 1) grid_barrier_step((unsigned)(t + 1) * NC);
    }
}

// ---------------- launch ----------------------------------------------------
extern "C" void kernel_launch(void* const* d_in, const int* in_sizes, int n_in,
                              void* d_out, int out_size)
{
    const float* x  = (const float*)d_in[0];
    const float* Wi = (const float*)d_in[1];
    const float* bi = (const float*)d_in[2];
    const float* Wh = (const float*)d_in[3];
    const float* bh = (const float*)d_in[4];
    float* out = (float*)d_out;

    float* xi_ptr;
    cudaGetSymbolAddress((void**)&xi_ptr, g_xi);

    cudaFuncSetAttribute(gru_mma_persist,
                         cudaFuncAttributeMaxDynamicSharedMemorySize, SMEM_TOTAL);
    cudaFuncSetAttribute(xi_mma,
                         cudaFuncAttributeMaxDynamicSharedMemorySize, SMEM_XI);

    // prep: fp16 conversions
    split_x<<<131072, 256>>>(x);
    split_wi<<<6144, 256>>>(Wi);
    // xi = x @ Wi + bi on tensor cores (fp16 single-term, 3 CTAs/SM)
    xi_mma<<<dim3(48, 512), 256, SMEM_XI>>>(bi, xi_ptr);
    // zero h buffer + barrier counter
    init_state<<<512, 256>>>();
    // whole 512-step recurrence on tensor cores (fp16 single-term W)
    gru_mma_persist<<<NC, 256, SMEM_TOTAL>>>(Wh, bh, out);
}

// round 12
// speedup vs baseline: 1.7002x; 1.1059x over previous
#include <cuda_runtime.h>
#include <cuda_bf16.h>
#include <cuda_fp16.h>
#include <math.h>
#include <stdint.h>

#define NC      128       // persistent CTAs; CTA owns hidden slice j0 = bid*8
#define TSTEPS  512

// ---------------- scratch (__device__ globals; no runtime allocation) ------
__device__ float g_xi[(size_t)512 * 128 * 3072];     // [T][B][3H]
__device__ __half g_xh[(size_t)128 * 512 * 512];     // x fp16
__device__ __half g_wih[(size_t)512 * 3072];         // Wi fp16
__device__ __half g_hf[2][128 * 1024];               // h fp16 (ping-pong)
__device__ unsigned g_bar_count;                     // monotone step counter

// ---------------- recurrence SMEM layout (dynamic, bytes) -------------------
// ws: W fragments fp16 (single term): [ks64][gate3][lane32][reg2] u32 = 48KB
// A staging: per-warp private, 4 bufs x (16 rows x 272B) = 17408 B/warp
#define WS_OFF     0
#define A_OFF      49152
#define A_BUF_SZ   4352          // 16 rows * 272B
#define A_WARP_SZ  17408         // 4 bufs
#define SMEM_TOTAL (49152 + 8 * 17408)   // 188416

// ---------------- xi mma SMEM layout (bytes) --------------------------------
#define XA_OFF   0
#define XA_BUFSZ 18432           // 128*144
#define XB_OFF   36864
#define XB_BUFSZ 9216            // 64*144
#define SMEM_XI  55296

// ---------------- PTX helpers ------------------------------------------------
__device__ __forceinline__ void mma_f16(float* c, const uint32_t* a,
                                        uint32_t b0, uint32_t b1) {
    asm volatile(
        "mma.sync.aligned.m16n8k16.row.col.f32.f16.f16.f32 "
        "{%0,%1,%2,%3}, {%4,%5,%6,%7}, {%8,%9}, {%0,%1,%2,%3};"
        : "+f"(c[0]), "+f"(c[1]), "+f"(c[2]), "+f"(c[3])
        : "r"(a[0]), "r"(a[1]), "r"(a[2]), "r"(a[3]), "r"(b0), "r"(b1));
}

__device__ __forceinline__ void ldmatrix_x4(uint32_t* a, uint32_t addr) {
    asm volatile(
        "ldmatrix.sync.aligned.m8n8.x4.shared.b16 {%0,%1,%2,%3}, [%4];"
        : "=r"(a[0]), "=r"(a[1]), "=r"(a[2]), "=r"(a[3]) : "r"(addr));
}

__device__ __forceinline__ void ldmatrix_x2t(uint32_t& b0, uint32_t& b1,
                                             uint32_t addr) {
    asm volatile(
        "ldmatrix.sync.aligned.m8n8.x2.trans.shared.b16 {%0,%1}, [%2];"
        : "=r"(b0), "=r"(b1) : "r"(addr));
}

__device__ __forceinline__ void cp16(uint32_t dst, const void* src) {
    asm volatile("cp.async.cg.shared.global [%0], [%1], 16;"
                 :: "r"(dst), "l"(src) : "memory");
}

// ---------------- fast gate math (ex2/rcp approx, ~2^-22 accurate) ----------
#define LOG2E 1.4426950408889634f
__device__ __forceinline__ float fexp2a(float x) {
    float r; asm("ex2.approx.f32 %0, %1;" : "=f"(r) : "f"(x)); return r;
}
__device__ __forceinline__ float frcpa(float x) {
    float r; asm("rcp.approx.f32 %0, %1;" : "=f"(r) : "f"(x)); return r;
}
__device__ __forceinline__ float fsigmoid(float x) {
    return frcpa(1.f + fexp2a(-x * LOG2E));
}
__device__ __forceinline__ float ftanh_(float x) {
    return 2.f * frcpa(1.f + fexp2a(-2.f * LOG2E * x)) - 1.f;
}

// ---------------- prep: x -> fp16 --------------------------------------------
__global__ __launch_bounds__(256) void split_x(const float* __restrict__ x)
{
    const size_t i = (size_t)blockIdx.x * 256 + threadIdx.x;
    g_xh[i] = __float2half_rn(x[i]);
}

// ---------------- prep: Wi -> fp16 -------------------------------------------
__global__ __launch_bounds__(256) void split_wi(const float* __restrict__ Wi)
{
    const size_t i = (size_t)blockIdx.x * 256 + threadIdx.x;
    g_wih[i] = __float2half_rn(Wi[i]);
}

// ---------------- xi = x @ Wi + bi  via mma.sync fp16 single-term ------------
// (unchanged, validated; tensor-issue-bound at ~0.67 ms)
__global__ __launch_bounds__(256, 3) void xi_mma(
    const float* __restrict__ bi, float* __restrict__ xi)
{
    extern __shared__ char sm[];
    const uint32_t su = (uint32_t)__cvta_generic_to_shared(sm);

    const int tid  = threadIdx.x;
    const int wid  = tid >> 5;
    const int lane = tid & 31;
    const int t    = blockIdx.y;
    const int n0   = blockIdx.x * 64;
    const int wm   = wid >> 1;
    const int wn   = wid & 1;

    float acc[2][4][4];
#pragma unroll
    for (int i = 0; i < 2; i++)
#pragma unroll
        for (int j = 0; j < 4; j++)
#pragma unroll
            for (int p = 0; p < 4; p++) acc[i][j][p] = 0.f;

    {
        const uint32_t ab = su + XA_OFF;
#pragma unroll
        for (int it = 0; it < 4; it++) {
            const int idx = tid + it * 256;
            const int r = idx >> 3, off = idx & 7;
            cp16(ab + r * 144 + off * 16,
                 &g_xh[((size_t)r * 512 + t) * 512 + off * 8]);
        }
#pragma unroll
        for (int it = 0; it < 2; it++) {
            const int idx = tid + it * 256;
            const int r = idx >> 3, off = idx & 7;
            cp16(su + XB_OFF + r * 144 + off * 16,
                 &g_wih[(size_t)r * 3072 + n0 + off * 8]);
        }
        asm volatile("cp.async.commit_group;" ::: "memory");
    }

#pragma unroll 1
    for (int c = 0; c < 8; c++) {
        asm volatile("cp.async.wait_group 0;" ::: "memory");
        __syncthreads();

        if (c < 7) {
            const int nb = (c + 1) & 1;
            const int kb = (c + 1) * 64;
            const uint32_t ab = su + XA_OFF + nb * XA_BUFSZ;
#pragma unroll
            for (int it = 0; it < 4; it++) {
                const int idx = tid + it * 256;
                const int r = idx >> 3, off = idx & 7;
                cp16(ab + r * 144 + off * 16,
                     &g_xh[((size_t)r * 512 + t) * 512 + kb + off * 8]);
            }
#pragma unroll
            for (int it = 0; it < 2; it++) {
                const int idx = tid + it * 256;
                const int r = idx >> 3, off = idx & 7;
                cp16(su + XB_OFF + nb * XB_BUFSZ + r * 144 + off * 16,
                     &g_wih[(size_t)(kb + r) * 3072 + n0 + off * 8]);
            }
            asm volatile("cp.async.commit_group;" ::: "memory");
        }

        const uint32_t abuf = su + XA_OFF + (c & 1) * XA_BUFSZ;
        const uint32_t bbuf = su + XB_OFF + (c & 1) * XB_BUFSZ;
#pragma unroll
        for (int kk = 0; kk < 4; kk++) {
            uint32_t a[2][4];
#pragma unroll
            for (int tile = 0; tile < 2; tile++) {
                const uint32_t aaddr = abuf
                    + (wm * 32 + tile * 16 + (lane & 15)) * 144
                    + (lane >> 4) * 16 + kk * 32;
                ldmatrix_x4(a[tile], aaddr);
            }
            uint32_t bf[4][2];
#pragma unroll
            for (int nt = 0; nt < 4; nt++) {
                const uint32_t baddr = bbuf
                    + (kk * 16 + (lane & 15)) * 144
                    + (wn * 32 + nt * 8) * 2;
                ldmatrix_x2t(bf[nt][0], bf[nt][1], baddr);
            }
#pragma unroll
            for (int tile = 0; tile < 2; tile++)
#pragma unroll
                for (int nt = 0; nt < 4; nt++)
                    mma_f16(acc[tile][nt], a[tile], bf[nt][0], bf[nt][1]);
        }
    }

    const int grp = lane >> 2;
    const int nlo = (lane & 3) * 2;
#pragma unroll
    for (int nt = 0; nt < 4; nt++) {
        const int n = n0 + wn * 32 + nt * 8 + nlo;
        const float2 bv = *reinterpret_cast<const float2*>(&bi[n]);
#pragma unroll
        for (int tile = 0; tile < 2; tile++) {
#pragma unroll
            for (int half = 0; half < 2; half++) {
                const int b = wm * 32 + tile * 16 + grp + half * 8;
                float2 o;
                o.x = acc[tile][nt][half * 2 + 0] + bv.x;
                o.y = acc[tile][nt][half * 2 + 1] + bv.y;
                *reinterpret_cast<float2*>(
                    &xi[((size_t)t * 128 + b) * 3072 + n]) = o;
            }
        }
    }
}

// ---------------- init: zero h buffer 0 + reset barrier counter -------------
__global__ void init_state()
{
    const int idx = blockIdx.x * 256 + threadIdx.x;   // < 131072
    g_hf[0][idx] = __float2half(0.f);
    if (idx == 0) g_bar_count = 0;
}

// ---------------- monotone-counter grid barrier (acquire-poll) --------------
__device__ __forceinline__ void grid_barrier_step(unsigned target)
{
    __syncthreads();
    if (threadIdx.x == 0) {
        asm volatile("red.release.gpu.global.add.u32 [%0], 1;"
                     :: "l"(&g_bar_count) : "memory");
        unsigned v;
        do {
            asm volatile("ld.acquire.gpu.global.u32 %0, [%1];"
                         : "=r"(v) : "l"(&g_bar_count) : "memory");
        } while (v < target);
    }
    __syncthreads();
}

// ---------------- persistent mma.sync GRU recurrence (fp16 1-term W) --------
// 128 CTAs x 256 threads (8 warps), CTA owns j-slice j0 = bid*8 (3 gates,
// N=24), warp w owns batch rows [w*16, w*16+16). Warp-private 4-stage
// cp.async A staging (3-ahead), monotone-counter barrier per step,
// approx-math gate epilogue.
__global__ __launch_bounds__(256, 1)
void gru_mma_persist(const float* __restrict__ Wh, const float* __restrict__ bh,
                     float* __restrict__ out)
{
    extern __shared__ char sm[];
    const uint32_t smem_u32 = (uint32_t)__cvta_generic_to_shared(sm);
    uint32_t* const ws = reinterpret_cast<uint32_t*>(sm + WS_OFF);

    const int tid  = threadIdx.x;
    const int wid  = tid >> 5;
    const int lane = tid & 31;
    const int bid  = blockIdx.x;
    const int j0   = bid * 8;

    // one-time: format Wh slice into fp16 mma B fragments (single term)
    for (int idx = tid; idx < 12288; idx += 256) {
        const int r    = idx & 1;
        const int l    = (idx >> 1) & 31;
        const int rest = idx >> 6;
        const int tt   = rest % 3;
        const int ks   = rest / 3;          // 0..63
        const int n = tt * 1024 + j0 + (l >> 2);
        const int k = ks * 16 + r * 8 + (l & 3) * 2;

        const __half e0 = __float2half_rn(Wh[(size_t)k * 3072 + n]);
        const __half e1 = __float2half_rn(Wh[(size_t)(k + 1) * 3072 + n]);
        ws[idx] = ((uint32_t)__half_as_ushort(e1) << 16)
                |  (uint32_t)__half_as_ushort(e0);
    }
    __syncthreads();

    const int b0 = wid * 16 + (lane >> 2);
    const int jb = j0 + (lane & 3) * 2;

    float bhv[3][2];
#pragma unroll
    for (int g = 0; g < 3; g++) {
        bhv[g][0] = bh[g * 1024 + jb];
        bhv[g][1] = bh[g * 1024 + jb + 1];
    }

    float hp[4];
#pragma unroll
    for (int p = 0; p < 4; p++) hp[p] = 0.f;

    const uint32_t awarp = smem_u32 + A_OFF + wid * A_WARP_SZ;
    const int arow = wid * 16;

#pragma unroll 1
    for (int t = 0; t < TSTEPS; t++) {
        const float* __restrict__ xi_t = g_xi + (size_t)t * 128 * 3072;
        const __half* __restrict__ hs = g_hf[t & 1];
        __half* __restrict__ hd = g_hf[(t + 1) & 1];

        // prologue FIRST: stage chunks 0..2 (h loads are the critical path)
#pragma unroll
        for (int pc = 0; pc < 3; pc++) {
            const uint32_t ab = awarp + pc * A_BUF_SZ;
#pragma unroll
            for (int it = 0; it < 8; it++) {
                const int idx = lane + it * 32;
                const int row = idx >> 4, off = idx & 15;
                cp16(ab + row * 272 + off * 16,
                     &hs[(arow + row) * 1024 + pc * 128 + off * 8]);
            }
            asm volatile("cp.async.commit_group;" ::: "memory");
        }

        // xi prefetch into registers (step-constant; hidden behind mainloop)
        float xiv[3][2][2];
#pragma unroll
        for (int g = 0; g < 3; g++)
#pragma unroll
            for (int rr = 0; rr < 2; rr++) {
                const float2 v = *reinterpret_cast<const float2*>(
                    &xi_t[(size_t)(b0 + rr * 8) * 3072 + g * 1024 + jb]);
                xiv[g][rr][0] = v.x; xiv[g][rr][1] = v.y;
            }

        float acc[3][4];
#pragma unroll
        for (int g = 0; g < 3; g++)
#pragma unroll
            for (int p = 0; p < 4; p++) acc[g][p] = 0.f;

#pragma unroll 1
        for (int c = 0; c < 8; c++) {
            if (c < 6)
                asm volatile("cp.async.wait_group 2;" ::: "memory");
            else if (c == 6)
                asm volatile("cp.async.wait_group 1;" ::: "memory");
            else
                asm volatile("cp.async.wait_group 0;" ::: "memory");
            __syncwarp();

            const uint32_t abuf = awarp + (c & 3) * A_BUF_SZ;
#pragma unroll
            for (int kk = 0; kk < 8; kk++) {
                uint32_t a[4];
                ldmatrix_x4(a, abuf + (lane & 15) * 272
                               + (lane >> 4) * 16 + kk * 32);
                const int ks = c * 8 + kk;
#pragma unroll
                for (int tt = 0; tt < 3; tt++) {
                    const uint32_t boff = smem_u32 + WS_OFF
                                        + (uint32_t)((ks * 3 + tt) * 256) + lane * 8;
                    uint32_t bh0, bh1;
                    asm("ld.shared.v2.u32 {%0,%1}, [%2];"
                        : "=r"(bh0), "=r"(bh1) : "r"(boff));
                    mma_f16(acc[tt], a, bh0, bh1);
                }
            }

            if (c < 5) {   // stage chunk c+3
                const uint32_t ab = awarp + ((c + 3) & 3) * A_BUF_SZ;
                const int kb = (c + 3) * 128;
#pragma unroll
                for (int it = 0; it < 8; it++) {
                    const int idx = lane + it * 32;
                    const int row = idx >> 4, off = idx & 15;
                    cp16(ab + row * 272 + off * 16,
                         &hs[(arow + row) * 1024 + kb + off * 8]);
                }
                asm volatile("cp.async.commit_group;" ::: "memory");
            }
        }

        // ---------------- gate epilogue (approx math, registers only) -------
#pragma unroll
        for (int rr = 0; rr < 2; rr++) {
            const int b = b0 + rr * 8;
            float hy2[2];
#pragma unroll
            for (int q = 0; q < 2; q++) {
                const int p = rr * 2 + q;
                const float hr = acc[0][p] + bhv[0][q];
                const float hz = acc[1][p] + bhv[1][q];
                const float hn = acc[2][p] + bhv[2][q];
                const float rg = fsigmoid(xiv[0][rr][q] + hr);
                const float zg = fsigmoid(xiv[1][rr][q] + hz);
                const float ng = ftanh_(xiv[2][rr][q] + rg * hn);
                const float hy = zg * ng + (1.f - zg) * hp[p];
                hp[p] = hy;
                hy2[q] = hy;
            }
            const __half e0 = __float2half_rn(hy2[0]);
            const __half e1 = __float2half_rn(hy2[1]);
            *reinterpret_cast<uint32_t*>(&hd[b * 1024 + jb]) =
                ((uint32_t)__half_as_ushort(e1) << 16)
                | (uint32_t)__half_as_ushort(e0);
            if (t == TSTEPS - 1) {
                float2 o; o.x = hy2[0]; o.y = hy2[1];
                *reinterpret_cast<float2*>(&out[b * 1024 + jb]) = o;
            }
        }

        if (t != TSTEPS - 1) grid_barrier_step((unsigned)(t + 1) * NC);
    }
}

// ---------------- launch ----------------------------------------------------
extern "C" void kernel_launch(void* const* d_in, const int* in_sizes, int n_in,
                              void* d_out, int out_size)
{
    const float* x  = (const float*)d_in[0];
    const float* Wi = (const float*)d_in[1];
    const float* bi = (const float*)d_in[2];
    const float* Wh = (const float*)d_in[3];
    const float* bh = (const float*)d_in[4];
    float* out = (float*)d_out;

    float* xi_ptr;
    cudaGetSymbolAddress((void**)&xi_ptr, g_xi);

    cudaFuncSetAttribute(gru_mma_persist,
                         cudaFuncAttributeMaxDynamicSharedMemorySize, SMEM_TOTAL);
    cudaFuncSetAttribute(xi_mma,
                         cudaFuncAttributeMaxDynamicSharedMemorySize, SMEM_XI);

    // prep: fp16 conversions
    split_x<<<131072, 256>>>(x);
    split_wi<<<6144, 256>>>(Wi);
    // xi = x @ Wi + bi on tensor cores (fp16 single-term, 3 CTAs/SM)
    xi_mma<<<dim3(48, 512), 256, SMEM_XI>>>(bi, xi_ptr);
    // zero h buffer + barrier counter
    init_state<<<512, 256>>>();
    // whole 512-step recurrence on tensor cores (fp16 single-term W)
    gru_mma_persist<<<NC, 256, SMEM_TOTAL>>>(Wh, bh, out);
}

// round 13
// speedup vs baseline: 1.8776x; 1.1043x over previous
#include <cuda_runtime.h>
#include <cuda_bf16.h>
#include <cuda_fp16.h>
#include <math.h>
#include <stdint.h>

#define NC      128       // persistent CTAs
#define TSTEPS  512

// ---------------- scratch (__device__ globals; no runtime allocation) ------
__device__ float g_xi[(size_t)512 * 128 * 3072];     // [T][B][3H]
__device__ __half g_xh[(size_t)128 * 512 * 512];     // x fp16
__device__ __half g_wih[(size_t)512 * 3072];         // Wi fp16
__device__ __half g_hf[2][128 * 1024];               // h fp16 (ping-pong)
__device__ unsigned g_bar_count;                     // monotone step counter

// ---------------- recurrence SMEM layout (dynamic, bytes) -------------------
// ws: W fragments fp16: [ks64][gate3][jhalf2][lane32][reg2] u32 = 96KB
// A staging: per-PAIR (2 warps share an m-tile), 4 bufs x (16 rows x 272B)
#define WS_OFF     0
#define A_OFF      98304
#define A_BUF_SZ   4352          // 16 rows * 272B
#define A_PAIR_SZ  17408         // 4 bufs
#define SMEM_TOTAL (98304 + 4 * 17408)   // 167936

// ---------------- xi mma SMEM layout (bytes) --------------------------------
#define XA_OFF   0
#define XA_BUFSZ 18432           // 128*144
#define XB_OFF   36864
#define XB_BUFSZ 9216            // 64*144
#define SMEM_XI  55296

// ---------------- PTX helpers ------------------------------------------------
__device__ __forceinline__ void mma_f16(float* c, const uint32_t* a,
                                        uint32_t b0, uint32_t b1) {
    asm volatile(
        "mma.sync.aligned.m16n8k16.row.col.f32.f16.f16.f32 "
        "{%0,%1,%2,%3}, {%4,%5,%6,%7}, {%8,%9}, {%0,%1,%2,%3};"
        : "+f"(c[0]), "+f"(c[1]), "+f"(c[2]), "+f"(c[3])
        : "r"(a[0]), "r"(a[1]), "r"(a[2]), "r"(a[3]), "r"(b0), "r"(b1));
}

__device__ __forceinline__ void ldmatrix_x4(uint32_t* a, uint32_t addr) {
    asm volatile(
        "ldmatrix.sync.aligned.m8n8.x4.shared.b16 {%0,%1,%2,%3}, [%4];"
        : "=r"(a[0]), "=r"(a[1]), "=r"(a[2]), "=r"(a[3]) : "r"(addr));
}

__device__ __forceinline__ void ldmatrix_x2t(uint32_t& b0, uint32_t& b1,
                                             uint32_t addr) {
    asm volatile(
        "ldmatrix.sync.aligned.m8n8.x2.trans.shared.b16 {%0,%1}, [%2];"
        : "=r"(b0), "=r"(b1) : "r"(addr));
}

__device__ __forceinline__ void cp16(uint32_t dst, const void* src) {
    asm volatile("cp.async.cg.shared.global [%0], [%1], 16;"
                 :: "r"(dst), "l"(src) : "memory");
}

// ---------------- fast gate math (ex2/rcp approx) ----------------------------
#define LOG2E 1.4426950408889634f
__device__ __forceinline__ float fexp2a(float x) {
    float r; asm("ex2.approx.f32 %0, %1;" : "=f"(r) : "f"(x)); return r;
}
__device__ __forceinline__ float frcpa(float x) {
    float r; asm("rcp.approx.f32 %0, %1;" : "=f"(r) : "f"(x)); return r;
}
__device__ __forceinline__ float fsigmoid(float x) {
    return frcpa(1.f + fexp2a(-x * LOG2E));
}
__device__ __forceinline__ float ftanh_(float x) {
    return 2.f * frcpa(1.f + fexp2a(-2.f * LOG2E * x)) - 1.f;
}

// ---------------- prep: x -> fp16 --------------------------------------------
__global__ __launch_bounds__(256) void split_x(const float* __restrict__ x)
{
    const size_t i = (size_t)blockIdx.x * 256 + threadIdx.x;
    g_xh[i] = __float2half_rn(x[i]);
}

// ---------------- prep: Wi -> fp16 -------------------------------------------
__global__ __launch_bounds__(256) void split_wi(const float* __restrict__ Wi)
{
    const size_t i = (size_t)blockIdx.x * 256 + threadIdx.x;
    g_wih[i] = __float2half_rn(Wi[i]);
}

// ---------------- xi = x @ Wi + bi  via mma.sync fp16 single-term ------------
// (unchanged, validated; tensor-issue-bound at ~0.67 ms)
__global__ __launch_bounds__(256, 3) void xi_mma(
    const float* __restrict__ bi, float* __restrict__ xi)
{
    extern __shared__ char sm[];
    const uint32_t su = (uint32_t)__cvta_generic_to_shared(sm);

    const int tid  = threadIdx.x;
    const int wid  = tid >> 5;
    const int lane = tid & 31;
    const int t    = blockIdx.y;
    const int n0   = blockIdx.x * 64;
    const int wm   = wid >> 1;
    const int wn   = wid & 1;

    float acc[2][4][4];
#pragma unroll
    for (int i = 0; i < 2; i++)
#pragma unroll
        for (int j = 0; j < 4; j++)
#pragma unroll
            for (int p = 0; p < 4; p++) acc[i][j][p] = 0.f;

    {
        const uint32_t ab = su + XA_OFF;
#pragma unroll
        for (int it = 0; it < 4; it++) {
            const int idx = tid + it * 256;
            const int r = idx >> 3, off = idx & 7;
            cp16(ab + r * 144 + off * 16,
                 &g_xh[((size_t)r * 512 + t) * 512 + off * 8]);
        }
#pragma unroll
        for (int it = 0; it < 2; it++) {
            const int idx = tid + it * 256;
            const int r = idx >> 3, off = idx & 7;
            cp16(su + XB_OFF + r * 144 + off * 16,
                 &g_wih[(size_t)r * 3072 + n0 + off * 8]);
        }
        asm volatile("cp.async.commit_group;" ::: "memory");
    }

#pragma unroll 1
    for (int c = 0; c < 8; c++) {
        asm volatile("cp.async.wait_group 0;" ::: "memory");
        __syncthreads();

        if (c < 7) {
            const int nb = (c + 1) & 1;
            const int kb = (c + 1) * 64;
            const uint32_t ab = su + XA_OFF + nb * XA_BUFSZ;
#pragma unroll
            for (int it = 0; it < 4; it++) {
                const int idx = tid + it * 256;
                const int r = idx >> 3, off = idx & 7;
                cp16(ab + r * 144 + off * 16,
                     &g_xh[((size_t)r * 512 + t) * 512 + kb + off * 8]);
            }
#pragma unroll
            for (int it = 0; it < 2; it++) {
                const int idx = tid + it * 256;
                const int r = idx >> 3, off = idx & 7;
                cp16(su + XB_OFF + nb * XB_BUFSZ + r * 144 + off * 16,
                     &g_wih[(size_t)(kb + r) * 3072 + n0 + off * 8]);
            }
            asm volatile("cp.async.commit_group;" ::: "memory");
        }

        const uint32_t abuf = su + XA_OFF + (c & 1) * XA_BUFSZ;
        const uint32_t bbuf = su + XB_OFF + (c & 1) * XB_BUFSZ;
#pragma unroll
        for (int kk = 0; kk < 4; kk++) {
            uint32_t a[2][4];
#pragma unroll
            for (int tile = 0; tile < 2; tile++) {
                const uint32_t aaddr = abuf
                    + (wm * 32 + tile * 16 + (lane & 15)) * 144
                    + (lane >> 4) * 16 + kk * 32;
                ldmatrix_x4(a[tile], aaddr);
            }
            uint32_t bf[4][2];
#pragma unroll
            for (int nt = 0; nt < 4; nt++) {
                const uint32_t baddr = bbuf
                    + (kk * 16 + (lane & 15)) * 144
                    + (wn * 32 + nt * 8) * 2;
                ldmatrix_x2t(bf[nt][0], bf[nt][1], baddr);
            }
#pragma unroll
            for (int tile = 0; tile < 2; tile++)
#pragma unroll
                for (int nt = 0; nt < 4; nt++)
                    mma_f16(acc[tile][nt], a[tile], bf[nt][0], bf[nt][1]);
        }
    }

    const int grp = lane >> 2;
    const int nlo = (lane & 3) * 2;
#pragma unroll
    for (int nt = 0; nt < 4; nt++) {
        const int n = n0 + wn * 32 + nt * 8 + nlo;
        const float2 bv = *reinterpret_cast<const float2*>(&bi[n]);
#pragma unroll
        for (int tile = 0; tile < 2; tile++) {
#pragma unroll
            for (int half = 0; half < 2; half++) {
                const int b = wm * 32 + tile * 16 + grp + half * 8;
                float2 o;
                o.x = acc[tile][nt][half * 2 + 0] + bv.x;
                o.y = acc[tile][nt][half * 2 + 1] + bv.y;
                *reinterpret_cast<float2*>(
                    &xi[((size_t)t * 128 + b) * 3072 + n]) = o;
            }
        }
    }
}

// ---------------- init: zero h buffer 0 + reset barrier counter -------------
__global__ void init_state()
{
    const int idx = blockIdx.x * 256 + threadIdx.x;   // < 131072
    g_hf[0][idx] = __float2half(0.f);
    if (idx == 0) g_bar_count = 0;
}

// ---------------- monotone-counter grid barrier (acquire-poll) --------------
__device__ __forceinline__ void grid_barrier_step(unsigned target)
{
    __syncthreads();
    if (threadIdx.x == 0) {
        asm volatile("red.release.gpu.global.add.u32 [%0], 1;"
                     :: "l"(&g_bar_count) : "memory");
        unsigned v;
        do {
            asm volatile("ld.acquire.gpu.global.u32 %0, [%1];"
                         : "=r"(v) : "l"(&g_bar_count) : "memory");
        } while (v < target);
    }
    __syncthreads();
}

// ---------------- persistent mma.sync GRU recurrence -------------------------
// 128 CTAs x 256 threads. CTA (jg = bid>>1, bhalf = bid&1) owns j-slice
// j0 = jg*16 (3 gates, N=48) for batch rows [bhalf*64, bhalf*64+64).
// -> h L2 traffic halves vs R12 (16 MB/step) with tensor work unchanged.
// Warp w: m-tile mw = w>>1 (16 rows), j-half nh = w&1 (8 cols x 3 gates).
// The two warps of a pair (same mw) share one A staging region: each loads
// half, synced by a named barrier (id 1+mw, 64 threads) per chunk.
__global__ __launch_bounds__(256, 1)
void gru_mma_persist(const float* __restrict__ Wh, const float* __restrict__ bh,
                     float* __restrict__ out)
{
    extern __shared__ char sm[];
    const uint32_t smem_u32 = (uint32_t)__cvta_generic_to_shared(sm);
    uint32_t* const ws = reinterpret_cast<uint32_t*>(sm + WS_OFF);

    const int tid  = threadIdx.x;
    const int wid  = tid >> 5;
    const int lane = tid & 31;
    const int bid  = blockIdx.x;
    const int jg    = bid >> 1;
    const int bhalf = bid & 1;
    const int j0    = jg * 16;
    const int row0  = bhalf * 64;
    const int mw    = wid >> 1;       // 0..3 (m-tile)
    const int nh    = wid & 1;        // 0..1 (j-half)

    // one-time: format Wh slice into fp16 mma B fragments
    // layout u32 idx = ((ks*3 + tt)*2 + nh)*64 + l*2 + r
    for (int idx = tid; idx < 24576; idx += 256) {
        const int r     = idx & 1;
        const int l     = (idx >> 1) & 31;
        const int rest  = idx >> 6;           // 0..383
        const int nhf   = rest & 1;
        const int rest2 = rest >> 1;          // 0..191
        const int tt    = rest2 % 3;
        const int ks    = rest2 / 3;          // 0..63
        const int n = tt * 1024 + j0 + nhf * 8 + (l >> 2);
        const int k = ks * 16 + r * 8 + (l & 3) * 2;

        const __half e0 = __float2half_rn(Wh[(size_t)k * 3072 + n]);
        const __half e1 = __float2half_rn(Wh[(size_t)(k + 1) * 3072 + n]);
        ws[idx] = ((uint32_t)__half_as_ushort(e1) << 16)
                |  (uint32_t)__half_as_ushort(e0);
    }
    __syncthreads();

    const int b0r = row0 + mw * 16 + (lane >> 2);   // rows b0r, b0r+8
    const int jb  = j0 + nh * 8 + (lane & 3) * 2;   // cols jb, jb+1

    float bhv[3][2];
#pragma unroll
    for (int g = 0; g < 3; g++) {
        bhv[g][0] = bh[g * 1024 + jb];
        bhv[g][1] = bh[g * 1024 + jb + 1];
    }

    float hp[4];
#pragma unroll
    for (int p = 0; p < 4; p++) hp[p] = 0.f;

    const uint32_t apair = smem_u32 + A_OFF + mw * A_PAIR_SZ;
    const int arow = row0 + mw * 16;     // pair's first batch row
    const int baridx = 1 + mw;           // named barrier per pair

#pragma unroll 1
    for (int t = 0; t < TSTEPS; t++) {
        const float* __restrict__ xi_t = g_xi + (size_t)t * 128 * 3072;
        const __half* __restrict__ hs = g_hf[t & 1];
        __half* __restrict__ hd = g_hf[(t + 1) & 1];

        // prologue FIRST: stage chunks 0..2 (each warp loads its half)
#pragma unroll
        for (int pc = 0; pc < 3; pc++) {
            const uint32_t ab = apair + pc * A_BUF_SZ;
#pragma unroll
            for (int it = 0; it < 4; it++) {
                const int idx = nh * 128 + lane + it * 32;   // 0..255 over pair
                const int row = idx >> 4, off = idx & 15;
                cp16(ab + row * 272 + off * 16,
                     &hs[(arow + row) * 1024 + pc * 128 + off * 8]);
            }
            asm volatile("cp.async.commit_group;" ::: "memory");
        }

        // xi prefetch into registers
        float xiv[3][2][2];
#pragma unroll
        for (int g = 0; g < 3; g++)
#pragma unroll
            for (int rr = 0; rr < 2; rr++) {
                const float2 v = *reinterpret_cast<const float2*>(
                    &xi_t[(size_t)(b0r + rr * 8) * 3072 + g * 1024 + jb]);
                xiv[g][rr][0] = v.x; xiv[g][rr][1] = v.y;
            }

        float acc[3][4];
#pragma unroll
        for (int g = 0; g < 3; g++)
#pragma unroll
            for (int p = 0; p < 4; p++) acc[g][p] = 0.f;

#pragma unroll 1
        for (int c = 0; c < 8; c++) {
            if (c < 6)
                asm volatile("cp.async.wait_group 2;" ::: "memory");
            else if (c == 6)
                asm volatile("cp.async.wait_group 1;" ::: "memory");
            else
                asm volatile("cp.async.wait_group 0;" ::: "memory");
            // pair barrier: partner's half of this chunk is visible
            asm volatile("bar.sync %0, 64;" :: "r"(baridx) : "memory");

            const uint32_t abuf = apair + (c & 3) * A_BUF_SZ;
#pragma unroll
            for (int kk = 0; kk < 8; kk++) {
                uint32_t a[4];
                ldmatrix_x4(a, abuf + (lane & 15) * 272
                               + (lane >> 4) * 16 + kk * 32);
                const int ks = c * 8 + kk;
#pragma unroll
                for (int tt = 0; tt < 3; tt++) {
                    const uint32_t boff = smem_u32 + WS_OFF
                        + (uint32_t)((((ks * 3 + tt) * 2) + nh) * 256) + lane * 8;
                    uint32_t bh0, bh1;
                    asm("ld.shared.v2.u32 {%0,%1}, [%2];"
                        : "=r"(bh0), "=r"(bh1) : "r"(boff));
                    mma_f16(acc[tt], a, bh0, bh1);
                }
            }

            if (c < 5) {   // stage chunk c+3 (each warp its half)
                const uint32_t ab = apair + ((c + 3) & 3) * A_BUF_SZ;
                const int kb = (c + 3) * 128;
#pragma unroll
                for (int it = 0; it < 4; it++) {
                    const int idx = nh * 128 + lane + it * 32;
                    const int row = idx >> 4, off = idx & 15;
                    cp16(ab + row * 272 + off * 16,
                         &hs[(arow + row) * 1024 + kb + off * 8]);
                }
                asm volatile("cp.async.commit_group;" ::: "memory");
            }
        }

        // ---------------- gate epilogue (approx math, registers only) -------
#pragma unroll
        for (int rr = 0; rr < 2; rr++) {
            const int b = b0r + rr * 8;
            float hy2[2];
#pragma unroll
            for (int q = 0; q < 2; q++) {
                const int p = rr * 2 + q;
                const float hr = acc[0][p] + bhv[0][q];
                const float hz = acc[1][p] + bhv[1][q];
                const float hn = acc[2][p] + bhv[2][q];
                const float rg = fsigmoid(xiv[0][rr][q] + hr);
                const float zg = fsigmoid(xiv[1][rr][q] + hz);
                const float ng = ftanh_(xiv[2][rr][q] + rg * hn);
                const float hy = zg * ng + (1.f - zg) * hp[p];
                hp[p] = hy;
                hy2[q] = hy;
            }
            const __half e0 = __float2half_rn(hy2[0]);
            const __half e1 = __float2half_rn(hy2[1]);
            *reinterpret_cast<uint32_t*>(&hd[b * 1024 + jb]) =
                ((uint32_t)__half_as_ushort(e1) << 16)
                | (uint32_t)__half_as_ushort(e0);
            if (t == TSTEPS - 1) {
                float2 o; o.x = hy2[0]; o.y = hy2[1];
                *reinterpret_cast<float2*>(&out[b * 1024 + jb]) = o;
            }
        }

        if (t != TSTEPS - 1) grid_barrier_step((unsigned)(t + 1) * NC);
    }
}

// ---------------- launch ----------------------------------------------------
extern "C" void kernel_launch(void* const* d_in, const int* in_sizes, int n_in,
                              void* d_out, int out_size)
{
    const float* x  = (const float*)d_in[0];
    const float* Wi = (const float*)d_in[1];
    const float* bi = (const float*)d_in[2];
    const float* Wh = (const float*)d_in[3];
    const float* bh = (const float*)d_in[4];
    float* out = (float*)d_out;

    float* xi_ptr;
    cudaGetSymbolAddress((void**)&xi_ptr, g_xi);

    cudaFuncSetAttribute(gru_mma_persist,
                         cudaFuncAttributeMaxDynamicSharedMemorySize, SMEM_TOTAL);
    cudaFuncSetAttribute(xi_mma,
                         cudaFuncAttributeMaxDynamicSharedMemorySize, SMEM_XI);

    // prep: fp16 conversions
    split_x<<<131072, 256>>>(x);
    split_wi<<<6144, 256>>>(Wi);
    // xi = x @ Wi + bi on tensor cores (fp16 single-term, 3 CTAs/SM)
    xi_mma<<<dim3(48, 512), 256, SMEM_XI>>>(bi, xi_ptr);
    // zero h buffer + barrier counter
    init_state<<<512, 256>>>();
    // whole 512-step recurrence (halved h broadcast: M=64/CTA, N=48/CTA)
    gru_mma_persist<<<NC, 256, SMEM_TOTAL>>>(Wh, bh, out);
}